// round 3
// baseline (speedup 1.0000x reference)
#include <cuda_runtime.h>
#include <cstdint>

#define B_    16
#define T_    256
#define MEL_  1024
#define D_    512
#define H_    8
#define L_    4
#define INTER_ 2048
#define OUT_  80

// ---------------- scratch (static device globals: no allocations) ----------
__device__ float g_x  [(size_t)B_*MEL_*D_];
__device__ float g_y  [(size_t)B_*MEL_*D_];
__device__ float g_ctx[(size_t)B_*MEL_*D_];
__device__ float g_qkv[(size_t)B_*MEL_*3*D_];
__device__ float g_h  [(size_t)B_*MEL_*INTER_];
__device__ int   g_idx[B_*MEL_];

__device__ __forceinline__ unsigned f2tf(float x)
{
    unsigned u;
    asm("cvt.rna.tf32.f32 %0, %1;" : "=r"(u) : "f"(x));
    return u;
}

__device__ __forceinline__ void mma8(float* c, const unsigned* a,
                                     unsigned b0, unsigned b1)
{
    asm volatile(
        "mma.sync.aligned.m16n8k8.row.col.f32.tf32.tf32.f32 "
        "{%0,%1,%2,%3}, {%4,%5,%6,%7}, {%8,%9}, {%0,%1,%2,%3};"
        : "+f"(c[0]), "+f"(c[1]), "+f"(c[2]), "+f"(c[3])
        : "r"(a[0]), "r"(a[1]), "r"(a[2]), "r"(a[3]), "r"(b0), "r"(b1));
}

// ---------------- embedding + positional encoding --------------------------
__global__ void embed_k(const int* __restrict__ tokens,
                        const float* __restrict__ emb,
                        float* __restrict__ x)
{
    int row = blockIdx.x;            // b*T + t
    int b   = row >> 8;              // T_=256
    int tok = tokens[row];
    int tid = threadIdx.x;           // 128 threads, float4 each
    float4 e = ((const float4*)(emb + (size_t)tok * D_))[tid];
    int d0 = tid * 4;
    const float c = 9.210340371976184f / (float)D_;   // ln(10000)/D
    float den0 = __expf(-(float)(d0)     * c);
    float den1 = __expf(-(float)(d0 + 2) * c);
    float a0 = (float)b * den0, a1 = (float)b * den1;
    float4 o;
    o.x = 2.f * e.x + sinf(a0);
    o.y = 2.f * e.y + cosf(a0);
    o.z = 2.f * e.z + sinf(a1);
    o.w = 2.f * e.w + cosf(a1);
    ((float4*)(x + (size_t)row * D_))[tid] = o;
}

// ---------------- 3xTF32 tensor-core GEMM  C = op(A) @ W + bias (+R) -------
// 128x128 CTA tile, BK=16, 8 warps each 32x64.
// Precision: A,B split hi+lo (tf32); acc += Ah*Bh + Al*Bh + Ah*Bl  (~fp32).
#define APIT 20
#define BPIT 136
#define ASZ  (128 * APIT)
#define BSZ  (16 * BPIT)
#define GEMM_SMEM ((4 * ASZ + 4 * BSZ) * 4)

template<int CONV, bool RELU, bool RESID, bool TRANS>
__global__ __launch_bounds__(256) void gemm_tc(
    const float* __restrict__ A, const float* __restrict__ W,
    const float* __restrict__ bias, const float* __restrict__ R,
    float* __restrict__ C, int N, int M, int Kd, int S, int Din)
{
    extern __shared__ unsigned dsm[];
    unsigned* As_h = dsm;                 // 2 * ASZ
    unsigned* As_l = As_h + 2 * ASZ;      // 2 * ASZ
    unsigned* Bs_h = As_l + 2 * ASZ;      // 2 * BSZ
    unsigned* Bs_l = Bs_h + 2 * BSZ;      // 2 * BSZ

    int tid  = threadIdx.x;
    int lane = tid & 31, warp = tid >> 5;
    int wm = warp & 3, wn = warp >> 2;
    int gr = lane >> 2, tig = lane & 3;
    int rowB = blockIdx.y * 128, colB = blockIdx.x * 128;

    float acc[2][8][4];
#pragma unroll
    for (int i = 0; i < 2; i++)
#pragma unroll
        for (int j = 0; j < 8; j++)
#pragma unroll
            for (int q = 0; q < 4; q++) acc[i][j][q] = 0.f;

    float4 aS[2], bS[2];

    auto ldgA = [&](int k0) {
#pragma unroll
        for (int i = 0; i < 2; i++) {
            int u  = tid + i * 256;
            int r  = rowB + (u >> 2);
            int kk = k0 + (u & 3) * 4;
            float4 v = make_float4(0.f, 0.f, 0.f, 0.f);
            if (CONV == 0) {
                v = *(const float4*)(A + (size_t)r * Kd + kk);
            } else {
                int bb = r / S, ss = r - bb * S;
                int kc = kk / Din, d = kk - kc * Din;
                int p  = ss + kc - 1;
                if (p >= 0 && p < S)
                    v = *(const float4*)(A + (size_t)(bb * S + p) * Din + d);
            }
            aS[i] = v;
        }
    };
    auto ldgB = [&](int k0) {
#pragma unroll
        for (int i = 0; i < 2; i++) {
            int u   = tid + i * 256;
            int kr  = u >> 5;
            int nc  = (u & 31) * 4;
            int col = colB + nc;
            float4 v = make_float4(0.f, 0.f, 0.f, 0.f);
            if (col < M)
                v = *(const float4*)(W + (size_t)(k0 + kr) * M + col);
            bS[i] = v;
        }
    };
    auto sts = [&](int s) {
#pragma unroll
        for (int i = 0; i < 2; i++) {
            int u = tid + i * 256;
            int r = u >> 2, ch = (u & 3) * 4;
            float4 a = aS[i];
            uint4 th, tl;
            th.x = f2tf(a.x); tl.x = f2tf(a.x - __uint_as_float(th.x));
            th.y = f2tf(a.y); tl.y = f2tf(a.y - __uint_as_float(th.y));
            th.z = f2tf(a.z); tl.z = f2tf(a.z - __uint_as_float(th.z));
            th.w = f2tf(a.w); tl.w = f2tf(a.w - __uint_as_float(th.w));
            *(uint4*)&As_h[s * ASZ + r * APIT + ch] = th;
            *(uint4*)&As_l[s * ASZ + r * APIT + ch] = tl;
            int kr = u >> 5, nc = (u & 31) * 4;
            float4 b = bS[i];
            uint4 bh, bl;
            bh.x = f2tf(b.x); bl.x = f2tf(b.x - __uint_as_float(bh.x));
            bh.y = f2tf(b.y); bl.y = f2tf(b.y - __uint_as_float(bh.y));
            bh.z = f2tf(b.z); bl.z = f2tf(b.z - __uint_as_float(bh.z));
            bh.w = f2tf(b.w); bl.w = f2tf(b.w - __uint_as_float(bh.w));
            *(uint4*)&Bs_h[s * BSZ + kr * BPIT + nc] = bh;
            *(uint4*)&Bs_l[s * BSZ + kr * BPIT + nc] = bl;
        }
    };
    auto compute = [&](int s) {
#pragma unroll
        for (int ks = 0; ks < 2; ks++) {
            int kb = ks * 8;
            unsigned afh[2][4], afl[2][4];
#pragma unroll
            for (int mi = 0; mi < 2; mi++) {
                int m = wm * 32 + mi * 16 + gr;
                int o0 = s * ASZ + m * APIT + kb + tig;
                int o1 = s * ASZ + (m + 8) * APIT + kb + tig;
                afh[mi][0] = As_h[o0];     afh[mi][1] = As_h[o1];
                afh[mi][2] = As_h[o0 + 4]; afh[mi][3] = As_h[o1 + 4];
                afl[mi][0] = As_l[o0];     afl[mi][1] = As_l[o1];
                afl[mi][2] = As_l[o0 + 4]; afl[mi][3] = As_l[o1 + 4];
            }
#pragma unroll
            for (int ni = 0; ni < 8; ni++) {
                int n  = wn * 64 + ni * 8 + gr;
                int ob = s * BSZ + (kb + tig) * BPIT + n;
                unsigned bh0 = Bs_h[ob], bh1 = Bs_h[ob + 4 * BPIT];
                unsigned bl0 = Bs_l[ob], bl1 = Bs_l[ob + 4 * BPIT];
#pragma unroll
                for (int mi = 0; mi < 2; mi++) {
                    mma8(acc[mi][ni], afh[mi], bh0, bh1);
                    mma8(acc[mi][ni], afl[mi], bh0, bh1);
                    mma8(acc[mi][ni], afh[mi], bl0, bl1);
                }
            }
        }
    };

    ldgA(0); ldgB(0);
    int s = 0;
    for (int k0 = 0; k0 < Kd; k0 += 16) {
        sts(s);
        __syncthreads();
        if (k0 + 16 < Kd) { ldgA(k0 + 16); ldgB(k0 + 16); }
        compute(s);
        s ^= 1;
        if (k0 + 16 < Kd) __syncthreads();
    }

#pragma unroll
    for (int mi = 0; mi < 2; mi++) {
        int r0 = rowB + wm * 32 + mi * 16 + gr;
#pragma unroll
        for (int ni = 0; ni < 8; ni++) {
            int c0 = colB + wn * 64 + ni * 8 + tig * 2;
#pragma unroll
            for (int hh = 0; hh < 2; hh++) {
                int r = r0 + hh * 8;
#pragma unroll
                for (int cc = 0; cc < 2; cc++) {
                    int col = c0 + cc;
                    if (col >= M) continue;
                    float v = acc[mi][ni][hh * 2 + cc] + bias[col];
                    if (RESID) v += R[(size_t)r * M + col];
                    if (RELU)  v = fmaxf(v, 0.f);
                    if (!TRANS) {
                        C[(size_t)r * M + col] = v;
                    } else {
                        int bb = r >> 10, f = r & 1023;
                        C[((size_t)(bb * OUT_ + col)) * MEL_ + f] = v;
                    }
                }
            }
        }
    }
}

// ---------------- tensor-core flash attention (tf32) -----------------------
// 4 warps, 64 q rows per CTA (16 per warp), kv chunks of 64.
#define ATP 68
#define ATTN_SMEM (3 * 64 * ATP * 4)
__global__ __launch_bounds__(128) void attn_tc(const float* __restrict__ qkv,
                                               const int* __restrict__ lens,
                                               float* __restrict__ ctx, int S)
{
    extern __shared__ unsigned asmm[];
    unsigned* Ps = asmm;              // Q tile first, then reused for P
    unsigned* Ks = Ps + 64 * ATP;
    unsigned* Vt = Ks + 64 * ATP;

    int tid  = threadIdx.x;
    int lane = tid & 31, warp = tid >> 5;
    int gr = lane >> 2, tig = lane & 3;
    int b = blockIdx.y >> 3, h = blockIdx.y & 7;
    int qt = blockIdx.x;
    int len = lens[b];
    const float* base = qkv + (size_t)b * S * (3 * D_);

    // ---- load Q tile (scaled by 1/8, tf32) ----
#pragma unroll
    for (int i = 0; i < 8; i++) {
        int idx = i * 128 + tid;
        int tok = idx >> 4, d4 = (idx & 15) * 4;
        float4 q = *(const float4*)(base + (size_t)(qt * 64 + tok) * (3 * D_)
                                    + h * 64 + d4);
        uint4 t;
        t.x = f2tf(q.x * 0.125f); t.y = f2tf(q.y * 0.125f);
        t.z = f2tf(q.z * 0.125f); t.w = f2tf(q.w * 0.125f);
        *(uint4*)&Ps[tok * ATP + d4] = t;
    }
    __syncthreads();

    int q0 = warp * 16;
    unsigned qf[8][4];
#pragma unroll
    for (int kk = 0; kk < 8; kk++) {
        int o0 = (q0 + gr) * ATP + kk * 8 + tig;
        int o1 = (q0 + gr + 8) * ATP + kk * 8 + tig;
        qf[kk][0] = Ps[o0];     qf[kk][1] = Ps[o1];
        qf[kk][2] = Ps[o0 + 4]; qf[kk][3] = Ps[o1 + 4];
    }

    float m0 = -3.0e38f, m1 = -3.0e38f, l0 = 0.f, l1 = 0.f;
    float o[8][4];
#pragma unroll
    for (int i = 0; i < 8; i++)
#pragma unroll
        for (int j = 0; j < 4; j++) o[i][j] = 0.f;

    int nkt = S >> 6;
    for (int kt = 0; kt < nkt; kt++) {
        __syncthreads();
        // K tile: row-major [tok][d]
#pragma unroll
        for (int i = 0; i < 8; i++) {
            int idx = i * 128 + tid;
            int tok = idx >> 4, d4 = (idx & 15) * 4;
            float4 k = *(const float4*)(base
                + (size_t)(kt * 64 + tok) * (3 * D_) + D_ + h * 64 + d4);
            uint4 t;
            t.x = f2tf(k.x); t.y = f2tf(k.y); t.z = f2tf(k.z); t.w = f2tf(k.w);
            *(uint4*)&Ks[tok * ATP + d4] = t;
        }
        // V tile transposed: Vt[d][tok]
        {
            int d = tid & 63, tq0 = tid >> 6;
#pragma unroll
            for (int i = 0; i < 8; i++) {
                int tok = (tq0 * 8 + i) * 4;
                const float* vb = base + (size_t)(kt * 64 + tok) * (3 * D_)
                                  + 2 * D_ + h * 64 + d;
                uint4 t;
                t.x = f2tf(vb[0]);
                t.y = f2tf(vb[3 * D_]);
                t.z = f2tf(vb[6 * D_]);
                t.w = f2tf(vb[9 * D_]);
                *(uint4*)&Vt[d * ATP + tok] = t;
            }
        }
        __syncthreads();

        // ---- S = Q K^T ----
        float s[8][4];
#pragma unroll
        for (int nt = 0; nt < 8; nt++)
#pragma unroll
            for (int j = 0; j < 4; j++) s[nt][j] = 0.f;
#pragma unroll
        for (int kk = 0; kk < 8; kk++)
#pragma unroll
            for (int nt = 0; nt < 8; nt++) {
                int ob = (nt * 8 + gr) * ATP + kk * 8 + tig;
                mma8(s[nt], qf[kk], Ks[ob], Ks[ob + 4]);
            }

        // ---- mask + online softmax ----
        float mx0 = -3.0e38f, mx1 = -3.0e38f;
#pragma unroll
        for (int nt = 0; nt < 8; nt++) {
            int c0 = kt * 64 + nt * 8 + 2 * tig;
            if (c0 > len)     { s[nt][0] = -1.0e30f; s[nt][2] = -1.0e30f; }
            if (c0 + 1 > len) { s[nt][1] = -1.0e30f; s[nt][3] = -1.0e30f; }
            mx0 = fmaxf(mx0, fmaxf(s[nt][0], s[nt][1]));
            mx1 = fmaxf(mx1, fmaxf(s[nt][2], s[nt][3]));
        }
        mx0 = fmaxf(mx0, __shfl_xor_sync(0xffffffffu, mx0, 1));
        mx0 = fmaxf(mx0, __shfl_xor_sync(0xffffffffu, mx0, 2));
        mx1 = fmaxf(mx1, __shfl_xor_sync(0xffffffffu, mx1, 1));
        mx1 = fmaxf(mx1, __shfl_xor_sync(0xffffffffu, mx1, 2));
        float mn0 = fmaxf(m0, mx0), mn1 = fmaxf(m1, mx1);
        float sc0 = __expf(m0 - mn0), sc1 = __expf(m1 - mn1);
        float rs0 = 0.f, rs1 = 0.f;
#pragma unroll
        for (int nt = 0; nt < 8; nt++) {
            float p0 = __expf(s[nt][0] - mn0);
            float p1 = __expf(s[nt][1] - mn0);
            float p2 = __expf(s[nt][2] - mn1);
            float p3 = __expf(s[nt][3] - mn1);
            rs0 += p0 + p1; rs1 += p2 + p3;
            uint2 u0; u0.x = f2tf(p0); u0.y = f2tf(p1);
            uint2 u1; u1.x = f2tf(p2); u1.y = f2tf(p3);
            *(uint2*)&Ps[(q0 + gr) * ATP + nt * 8 + 2 * tig] = u0;
            *(uint2*)&Ps[(q0 + gr + 8) * ATP + nt * 8 + 2 * tig] = u1;
        }
        rs0 += __shfl_xor_sync(0xffffffffu, rs0, 1);
        rs0 += __shfl_xor_sync(0xffffffffu, rs0, 2);
        rs1 += __shfl_xor_sync(0xffffffffu, rs1, 1);
        rs1 += __shfl_xor_sync(0xffffffffu, rs1, 2);
        l0 = l0 * sc0 + rs0; l1 = l1 * sc1 + rs1;
        m0 = mn0; m1 = mn1;
#pragma unroll
        for (int nt = 0; nt < 8; nt++) {
            o[nt][0] *= sc0; o[nt][1] *= sc0;
            o[nt][2] *= sc1; o[nt][3] *= sc1;
        }
        __syncwarp();

        // ---- O += P V ----
#pragma unroll
        for (int kk = 0; kk < 8; kk++) {
            unsigned af[4];
            int o0i = (q0 + gr) * ATP + kk * 8 + tig;
            int o1i = (q0 + gr + 8) * ATP + kk * 8 + tig;
            af[0] = Ps[o0i];     af[1] = Ps[o1i];
            af[2] = Ps[o0i + 4]; af[3] = Ps[o1i + 4];
#pragma unroll
            for (int nt2 = 0; nt2 < 8; nt2++) {
                int ob = (nt2 * 8 + gr) * ATP + kk * 8 + tig;
                mma8(o[nt2], af, Vt[ob], Vt[ob + 4]);
            }
        }
    }

    float inv0 = 1.f / l0, inv1 = 1.f / l1;
    size_t r0 = (size_t)(b * S + qt * 64 + q0 + gr) * D_ + h * 64;
    size_t r1 = r0 + 8 * D_;
#pragma unroll
    for (int nt2 = 0; nt2 < 8; nt2++) {
        int col = nt2 * 8 + 2 * tig;
        ctx[r0 + col]     = o[nt2][0] * inv0;
        ctx[r0 + col + 1] = o[nt2][1] * inv0;
        ctx[r1 + col]     = o[nt2][2] * inv1;
        ctx[r1 + col + 1] = o[nt2][3] * inv1;
    }
}

// ---------------- layernorm (in place, D=512) -------------------------------
__global__ __launch_bounds__(128) void ln_k(float* __restrict__ x,
                                            const float* __restrict__ g,
                                            const float* __restrict__ bt)
{
    __shared__ float sm8[8];
    int row = blockIdx.x, tid = threadIdx.x;
    float4* xr = (float4*)(x + (size_t)row * D_);
    float4 v = xr[tid];
    float s = v.x + v.y + v.z + v.w;
#pragma unroll
    for (int o = 16; o; o >>= 1) s += __shfl_xor_sync(0xffffffffu, s, o);
    if ((tid & 31) == 0) sm8[tid >> 5] = s;
    __syncthreads();
    float mean = (sm8[0] + sm8[1] + sm8[2] + sm8[3]) * (1.f / (float)D_);
    float d0 = v.x - mean, d1 = v.y - mean, d2 = v.z - mean, d3 = v.w - mean;
    float q = d0 * d0 + d1 * d1 + d2 * d2 + d3 * d3;
#pragma unroll
    for (int o = 16; o; o >>= 1) q += __shfl_xor_sync(0xffffffffu, q, o);
    if ((tid & 31) == 0) sm8[4 + (tid >> 5)] = q;
    __syncthreads();
    float var = (sm8[4] + sm8[5] + sm8[6] + sm8[7]) * (1.f / (float)D_);
    float inv = rsqrtf(var + 1e-5f);
    float4 g4 = ((const float4*)g)[tid];
    float4 b4 = ((const float4*)bt)[tid];
    v.x = d0 * inv * g4.x + b4.x;
    v.y = d1 * inv * g4.y + b4.y;
    v.z = d2 * inv * g4.z + b4.z;
    v.w = d3 * inv * g4.w + b4.w;
    xr[tid] = v;
}

// ---------------- length regulator ------------------------------------------
__global__ void regidx_k(const int* __restrict__ dur, int* __restrict__ idx)
{
    __shared__ int cums[T_];
    int b = blockIdx.x, tid = threadIdx.x;
    cums[tid] = dur[b * T_ + tid];
    __syncthreads();
    if (tid == 0) {
        int a = 0;
        for (int t = 0; t < T_; t++) { a += cums[t]; cums[t] = a; }
    }
    __syncthreads();
    for (int f = tid; f < MEL_; f += T_) {
        int lo = 0, hi = T_;
        while (lo < hi) {
            int mid = (lo + hi) >> 1;
            if (cums[mid] <= f) lo = mid + 1; else hi = mid;
        }
        idx[b * MEL_ + f] = (lo > T_ - 1) ? (T_ - 1) : lo;
    }
}

__global__ void gather_k(const float* __restrict__ enc, const int* __restrict__ idx,
                         const int* __restrict__ mlen, float* __restrict__ out)
{
    int row = blockIdx.x;            // b*MEL + f
    int b = row >> 10, f = row & 1023;
    float keep = (f <= mlen[b]) ? 1.f : 0.f;
    int t = idx[row];
    int tid = threadIdx.x;
    float4 v = ((const float4*)(enc + (size_t)(b * T_ + t) * D_))[tid];
    v.x *= keep; v.y *= keep; v.z *= keep; v.w *= keep;
    ((float4*)(out + (size_t)row * D_))[tid] = v;
}

// ---------------- driver -----------------------------------------------------
extern "C" void kernel_launch(void* const* d_in, const int* in_sizes, int n_in,
                              void* d_out, int out_size)
{
    const int* tokens = (const int*)d_in[0];
    const int* tlen   = (const int*)d_in[1];
    const int* mlen   = (const int*)d_in[2];
    const int* dur    = (const int*)d_in[3];

    int ei = n_in - 27;
    if (ei < 0 || in_sizes[ei] != 256 * D_) {
        for (int i = 0; i < n_in; i++)
            if (in_sizes[i] == 256 * D_) { ei = i; break; }
    }
    const float* emb = (const float*)d_in[ei];
    const float* P[26];
    for (int i = 0; i < 26; i++) P[i] = (const float*)d_in[ei + 1 + i];

    float *gx, *gy, *gctx, *gqkv, *gh;
    int* gidx;
    cudaGetSymbolAddress((void**)&gx,   g_x);
    cudaGetSymbolAddress((void**)&gy,   g_y);
    cudaGetSymbolAddress((void**)&gctx, g_ctx);
    cudaGetSymbolAddress((void**)&gqkv, g_qkv);
    cudaGetSymbolAddress((void**)&gh,   g_h);
    cudaGetSymbolAddress((void**)&gidx, g_idx);

    cudaFuncSetAttribute(attn_tc, cudaFuncAttributeMaxDynamicSharedMemorySize,
                         ATTN_SMEM);
    cudaFuncSetAttribute(gemm_tc<0, false, false, false>,
                         cudaFuncAttributeMaxDynamicSharedMemorySize, GEMM_SMEM);
    cudaFuncSetAttribute(gemm_tc<0, false, true, false>,
                         cudaFuncAttributeMaxDynamicSharedMemorySize, GEMM_SMEM);
    cudaFuncSetAttribute(gemm_tc<1, true, false, false>,
                         cudaFuncAttributeMaxDynamicSharedMemorySize, GEMM_SMEM);
    cudaFuncSetAttribute(gemm_tc<1, false, true, false>,
                         cudaFuncAttributeMaxDynamicSharedMemorySize, GEMM_SMEM);
    cudaFuncSetAttribute(gemm_tc<0, false, false, true>,
                         cudaFuncAttributeMaxDynamicSharedMemorySize, GEMM_SMEM);

    embed_k<<<B_ * T_, 128>>>(tokens, emb, gx);

    auto runLayer = [&](const float* const* W, int l, float* x, float* y,
                        int S, const int* lens) {
        int N = B_ * S;
        const float* wqkv = W[0]  + (size_t)l * D_ * 3 * D_;
        const float* bqkv = W[1]  + (size_t)l * 3 * D_;
        const float* wo   = W[2]  + (size_t)l * D_ * D_;
        const float* bo   = W[3]  + (size_t)l * D_;
        const float* l1g  = W[4]  + (size_t)l * D_;
        const float* l1b  = W[5]  + (size_t)l * D_;
        const float* c1w  = W[6]  + (size_t)l * 3 * D_ * INTER_;
        const float* c1b  = W[7]  + (size_t)l * INTER_;
        const float* c2w  = W[8]  + (size_t)l * 3 * INTER_ * D_;
        const float* c2b  = W[9]  + (size_t)l * D_;
        const float* l2g  = W[10] + (size_t)l * D_;
        const float* l2b  = W[11] + (size_t)l * D_;

        gemm_tc<0, false, false, false><<<dim3(12, N / 128), 256, GEMM_SMEM>>>(
            x, wqkv, bqkv, nullptr, gqkv, N, 3 * D_, D_, S, D_);
        attn_tc<<<dim3(S / 64, B_ * H_), 128, ATTN_SMEM>>>(gqkv, lens, gctx, S);
        gemm_tc<0, false, true, false><<<dim3(4, N / 128), 256, GEMM_SMEM>>>(
            gctx, wo, bo, x, y, N, D_, D_, S, D_);
        ln_k<<<N, 128>>>(y, l1g, l1b);
        gemm_tc<1, true, false, false><<<dim3(16, N / 128), 256, GEMM_SMEM>>>(
            y, c1w, c1b, nullptr, gh, N, INTER_, 3 * D_, S, D_);
        gemm_tc<1, false, true, false><<<dim3(4, N / 128), 256, GEMM_SMEM>>>(
            gh, c2w, c2b, y, x, N, D_, 3 * INTER_, S, INTER_);
        ln_k<<<N, 128>>>(x, l2g, l2b);
    };

    for (int l = 0; l < L_; l++) runLayer(P, l, gx, gy, T_, tlen);

    regidx_k<<<B_, T_>>>(dur, gidx);
    gather_k<<<B_ * MEL_, 128>>>(gx, gidx, mlen, gy);

    for (int l = 0; l < L_; l++) runLayer(P + 12, l, gy, gx, MEL_, mlen);

    gemm_tc<0, false, false, true><<<dim3(1, (B_ * MEL_) / 128), 256, GEMM_SMEM>>>(
        gy, P[24], P[25], nullptr, (float*)d_out, B_ * MEL_, OUT_, D_, MEL_, D_);
}

// round 6
// speedup vs baseline: 1.9791x; 1.9791x over previous
#include <cuda_runtime.h>
#include <cstdint>

#define B_    16
#define T_    256
#define MEL_  1024
#define D_    512
#define H_    8
#define L_    4
#define INTER_ 2048
#define OUT_  80

// ---------------- scratch (static device globals: no allocations) ----------
__device__ float g_x  [(size_t)B_*MEL_*D_];
__device__ float g_y  [(size_t)B_*MEL_*D_];
__device__ float g_ctx[(size_t)B_*MEL_*D_];
__device__ float g_qkv[(size_t)B_*MEL_*3*D_];
__device__ float g_h  [(size_t)B_*MEL_*INTER_];
__device__ int   g_idx[B_*MEL_];

__device__ __forceinline__ unsigned f2tf(float x)
{
    unsigned u;
    asm("cvt.rna.tf32.f32 %0, %1;" : "=r"(u) : "f"(x));
    return u;
}

__device__ __forceinline__ void mma8(float* c, const unsigned* a,
                                     unsigned b0, unsigned b1)
{
    asm volatile(
        "mma.sync.aligned.m16n8k8.row.col.f32.tf32.tf32.f32 "
        "{%0,%1,%2,%3}, {%4,%5,%6,%7}, {%8,%9}, {%0,%1,%2,%3};"
        : "+f"(c[0]), "+f"(c[1]), "+f"(c[2]), "+f"(c[3])
        : "r"(a[0]), "r"(a[1]), "r"(a[2]), "r"(a[3]), "r"(b0), "r"(b1));
}

// ---------------- embedding + positional encoding --------------------------
__global__ void embed_k(const int* __restrict__ tokens,
                        const float* __restrict__ emb,
                        float* __restrict__ x)
{
    int row = blockIdx.x;            // b*T + t
    int b   = row >> 8;              // T_=256
    int tok = tokens[row];
    int tid = threadIdx.x;           // 128 threads, float4 each
    float4 e = ((const float4*)(emb + (size_t)tok * D_))[tid];
    int d0 = tid * 4;
    const float c = 9.210340371976184f / (float)D_;   // ln(10000)/D
    float den0 = __expf(-(float)(d0)     * c);
    float den1 = __expf(-(float)(d0 + 2) * c);
    float a0 = (float)b * den0, a1 = (float)b * den1;
    float4 o;
    o.x = 2.f * e.x + sinf(a0);
    o.y = 2.f * e.y + cosf(a0);
    o.z = 2.f * e.z + sinf(a1);
    o.w = 2.f * e.w + cosf(a1);
    ((float4*)(x + (size_t)row * D_))[tid] = o;
}

// ---------------- TF32 tensor-core GEMM  C = op(A) @ W + bias (+R) ---------
// 128x128 CTA tile, BK=16, 8 warps each 32x64, m16n8k8 tf32 HMMA.
// CONV==1: A is [B*S, Din], virtual K = 3*Din, SAME zero padding.
//          S = 1<<SLOG, Din = 1<<DLOG (all shifts, no division).
//          Address of (row r, tap kc, chan d) = A + (r + kc - 1)*Din + d,
//          valid iff (kc==1) | (kc==0 & ss>0) | (kc==2 & ss<S-1).
// TRANS==1: store C[row,col] at out[(b*OUT_+col)*MEL_ + f]  (row = b*MEL_+f)
#define APIT 20
#define BPIT 136

template<int CONV, int SLOG, int DLOG, bool RELU, bool RESID, bool TRANS>
__global__ __launch_bounds__(256) void gemm_tc(
    const float* __restrict__ A, const float* __restrict__ W,
    const float* __restrict__ bias, const float* __restrict__ R,
    float* __restrict__ C, int N, int M, int Kd)
{
    __shared__ unsigned As[2][128 * APIT];
    __shared__ unsigned Bs[2][16 * BPIT];

    int tid  = threadIdx.x;
    int lane = tid & 31, warp = tid >> 5;
    int wm = warp & 3, wn = warp >> 2;        // warp tile: rows wm*32, cols wn*64
    int gr = lane >> 2, tig = lane & 3;
    int rowB = blockIdx.y * 128, colB = blockIdx.x * 128;

    // per-thread A-load geometry (constant across K-loop)
    int akb = (tid & 3) * 4;                  // k-sub offset 0..12
    int rr0 = rowB + (tid >> 2);              // row for i=0
    int rr1 = rr0 + 64;                       // row for i=1
    bool lo0 = true, hi0 = true, lo1 = true, hi1 = true;
    if (CONV) {
        int SM1 = (1 << SLOG) - 1;
        int ss0 = rr0 & SM1, ss1 = rr1 & SM1;
        lo0 = ss0 > 0;  hi0 = ss0 < SM1;
        lo1 = ss1 > 0;  hi1 = ss1 < SM1;
    }
    // per-thread B-load geometry
    int bkt = tid >> 5;                       // 0..7 (two i-steps add +8)
    int bc  = (tid & 31) * 4;
    int bcol = colB + bc;

    float acc[2][8][4];
#pragma unroll
    for (int i = 0; i < 2; i++)
#pragma unroll
        for (int j = 0; j < 8; j++)
#pragma unroll
            for (int q = 0; q < 4; q++) acc[i][j][q] = 0.f;

    float4 aS[2], bS[2];

    auto ldgA = [&](int k0) {
        int kk = k0 + akb;
        if (CONV == 0) {
            aS[0] = *(const float4*)(A + (size_t)rr0 * Kd + kk);
            aS[1] = *(const float4*)(A + (size_t)rr1 * Kd + kk);
        } else {
            int kc = kk >> DLOG;
            int dd = kk & ((1 << DLOG) - 1);
            bool ok0 = (kc == 1) || (kc == 0 ? lo0 : hi0);
            bool ok1 = (kc == 1) || (kc == 0 ? lo1 : hi1);
            const float* p = A + ((size_t)(kc - 1) << DLOG) + dd;
            float4 z = make_float4(0.f, 0.f, 0.f, 0.f);
            aS[0] = ok0 ? *(const float4*)(p + ((size_t)rr0 << DLOG)) : z;
            aS[1] = ok1 ? *(const float4*)(p + ((size_t)rr1 << DLOG)) : z;
        }
    };
    auto ldgB = [&](int k0) {
        float4 z = make_float4(0.f, 0.f, 0.f, 0.f);
        bS[0] = (bcol < M) ? *(const float4*)(W + (size_t)(k0 + bkt) * M + bcol) : z;
        bS[1] = (bcol < M) ? *(const float4*)(W + (size_t)(k0 + bkt + 8) * M + bcol) : z;
    };
    auto sts = [&](int s) {
        int r = tid >> 2;
#pragma unroll
        for (int i = 0; i < 2; i++) {
            uint4 ta;
            ta.x = f2tf(aS[i].x); ta.y = f2tf(aS[i].y);
            ta.z = f2tf(aS[i].z); ta.w = f2tf(aS[i].w);
            *(uint4*)&As[s][(r + i * 64) * APIT + akb] = ta;
            uint4 tb;
            tb.x = f2tf(bS[i].x); tb.y = f2tf(bS[i].y);
            tb.z = f2tf(bS[i].z); tb.w = f2tf(bS[i].w);
            *(uint4*)&Bs[s][(bkt + i * 8) * BPIT + bc] = tb;
        }
    };
    auto compute = [&](int s) {
#pragma unroll
        for (int ks = 0; ks < 2; ks++) {
            int kb = ks * 8;
            unsigned af[2][4], bf[8][2];
#pragma unroll
            for (int mi = 0; mi < 2; mi++) {
                int m = wm * 32 + mi * 16 + gr;
                af[mi][0] = As[s][m * APIT + kb + tig];
                af[mi][1] = As[s][(m + 8) * APIT + kb + tig];
                af[mi][2] = As[s][m * APIT + kb + tig + 4];
                af[mi][3] = As[s][(m + 8) * APIT + kb + tig + 4];
            }
#pragma unroll
            for (int ni = 0; ni < 8; ni++) {
                int n = wn * 64 + ni * 8 + gr;
                bf[ni][0] = Bs[s][(kb + tig) * BPIT + n];
                bf[ni][1] = Bs[s][(kb + tig + 4) * BPIT + n];
            }
#pragma unroll
            for (int mi = 0; mi < 2; mi++)
#pragma unroll
                for (int ni = 0; ni < 8; ni++)
                    mma8(acc[mi][ni], af[mi], bf[ni][0], bf[ni][1]);
        }
    };

    ldgA(0); ldgB(0);
    int s = 0;
    for (int k0 = 0; k0 < Kd; k0 += 16) {
        sts(s);
        __syncthreads();
        if (k0 + 16 < Kd) { ldgA(k0 + 16); ldgB(k0 + 16); }
        compute(s);
        s ^= 1;
    }

#pragma unroll
    for (int mi = 0; mi < 2; mi++) {
        int r0 = rowB + wm * 32 + mi * 16 + gr;
#pragma unroll
        for (int ni = 0; ni < 8; ni++) {
            int c0 = colB + wn * 64 + ni * 8 + tig * 2;
#pragma unroll
            for (int hh = 0; hh < 2; hh++) {
                int r = r0 + hh * 8;
#pragma unroll
                for (int cc = 0; cc < 2; cc++) {
                    int col = c0 + cc;
                    if (col >= M) continue;
                    float v = acc[mi][ni][hh * 2 + cc] + bias[col];
                    if (RESID) v += R[(size_t)r * M + col];
                    if (RELU)  v = fmaxf(v, 0.f);
                    if (!TRANS) {
                        C[(size_t)r * M + col] = v;
                    } else {
                        int bb = r >> 10, f = r & 1023;
                        C[((size_t)(bb * OUT_ + col)) * MEL_ + f] = v;
                    }
                }
            }
        }
    }
}

// ---------------- tensor-core flash attention (tf32) -----------------------
// 4 warps, 64 q rows per CTA (16 per warp), kv chunks of 64.
#define ATP 68
#define ATTN_SMEM (3 * 64 * ATP * 4)
__global__ __launch_bounds__(128) void attn_tc(const float* __restrict__ qkv,
                                               const int* __restrict__ lens,
                                               float* __restrict__ ctx, int S)
{
    extern __shared__ unsigned asmm[];
    unsigned* Ps = asmm;              // Q tile first, then reused for P
    unsigned* Ks = Ps + 64 * ATP;
    unsigned* Vt = Ks + 64 * ATP;

    int tid  = threadIdx.x;
    int lane = tid & 31, warp = tid >> 5;
    int gr = lane >> 2, tig = lane & 3;
    int b = blockIdx.y >> 3, h = blockIdx.y & 7;
    int qt = blockIdx.x;
    int len = lens[b];
    const float* base = qkv + (size_t)b * S * (3 * D_);

    // ---- load Q tile (scaled by 1/8, tf32) ----
#pragma unroll
    for (int i = 0; i < 8; i++) {
        int idx = i * 128 + tid;
        int tok = idx >> 4, d4 = (idx & 15) * 4;
        float4 q = *(const float4*)(base + (size_t)(qt * 64 + tok) * (3 * D_)
                                    + h * 64 + d4);
        uint4 t;
        t.x = f2tf(q.x * 0.125f); t.y = f2tf(q.y * 0.125f);
        t.z = f2tf(q.z * 0.125f); t.w = f2tf(q.w * 0.125f);
        *(uint4*)&Ps[tok * ATP + d4] = t;
    }
    __syncthreads();

    int q0 = warp * 16;
    unsigned qf[8][4];
#pragma unroll
    for (int kk = 0; kk < 8; kk++) {
        int o0 = (q0 + gr) * ATP + kk * 8 + tig;
        int o1 = (q0 + gr + 8) * ATP + kk * 8 + tig;
        qf[kk][0] = Ps[o0];     qf[kk][1] = Ps[o1];
        qf[kk][2] = Ps[o0 + 4]; qf[kk][3] = Ps[o1 + 4];
    }

    float m0 = -3.0e38f, m1 = -3.0e38f, l0 = 0.f, l1 = 0.f;
    float o[8][4];
#pragma unroll
    for (int i = 0; i < 8; i++)
#pragma unroll
        for (int j = 0; j < 4; j++) o[i][j] = 0.f;

    // keys with kg > len are masked out -> only iterate tiles that intersect
    int nkt = S >> 6;
    int need = (len >> 6) + 1;
    if (need < nkt) nkt = need;

    for (int kt = 0; kt < nkt; kt++) {
        __syncthreads();
        // K tile: row-major [tok][d]
#pragma unroll
        for (int i = 0; i < 8; i++) {
            int idx = i * 128 + tid;
            int tok = idx >> 4, d4 = (idx & 15) * 4;
            float4 k = *(const float4*)(base
                + (size_t)(kt * 64 + tok) * (3 * D_) + D_ + h * 64 + d4);
            uint4 t;
            t.x = f2tf(k.x); t.y = f2tf(k.y); t.z = f2tf(k.z); t.w = f2tf(k.w);
            *(uint4*)&Ks[tok * ATP + d4] = t;
        }
        // V tile transposed: Vt[d][tok]
        {
            int d = tid & 63, tq0 = tid >> 6;
#pragma unroll
            for (int i = 0; i < 8; i++) {
                int tok = (tq0 * 8 + i) * 4;
                const float* vb = base + (size_t)(kt * 64 + tok) * (3 * D_)
                                  + 2 * D_ + h * 64 + d;
                uint4 t;
                t.x = f2tf(vb[0]);
                t.y = f2tf(vb[3 * D_]);
                t.z = f2tf(vb[6 * D_]);
                t.w = f2tf(vb[9 * D_]);
                *(uint4*)&Vt[d * ATP + tok] = t;
            }
        }
        __syncthreads();

        // ---- S = Q K^T ----
        float s[8][4];
#pragma unroll
        for (int nt = 0; nt < 8; nt++)
#pragma unroll
            for (int j = 0; j < 4; j++) s[nt][j] = 0.f;
#pragma unroll
        for (int kk = 0; kk < 8; kk++)
#pragma unroll
            for (int nt = 0; nt < 8; nt++) {
                int ob = (nt * 8 + gr) * ATP + kk * 8 + tig;
                mma8(s[nt], qf[kk], Ks[ob], Ks[ob + 4]);
            }

        // ---- mask + online softmax ----
        float mx0 = -3.0e38f, mx1 = -3.0e38f;
#pragma unroll
        for (int nt = 0; nt < 8; nt++) {
            int c0 = kt * 64 + nt * 8 + 2 * tig;
            if (c0 > len)     { s[nt][0] = -1.0e30f; s[nt][2] = -1.0e30f; }
            if (c0 + 1 > len) { s[nt][1] = -1.0e30f; s[nt][3] = -1.0e30f; }
            mx0 = fmaxf(mx0, fmaxf(s[nt][0], s[nt][1]));
            mx1 = fmaxf(mx1, fmaxf(s[nt][2], s[nt][3]));
        }
        mx0 = fmaxf(mx0, __shfl_xor_sync(0xffffffffu, mx0, 1));
        mx0 = fmaxf(mx0, __shfl_xor_sync(0xffffffffu, mx0, 2));
        mx1 = fmaxf(mx1, __shfl_xor_sync(0xffffffffu, mx1, 1));
        mx1 = fmaxf(mx1, __shfl_xor_sync(0xffffffffu, mx1, 2));
        float mn0 = fmaxf(m0, mx0), mn1 = fmaxf(m1, mx1);
        float sc0 = __expf(m0 - mn0), sc1 = __expf(m1 - mn1);
        float rs0 = 0.f, rs1 = 0.f;
#pragma unroll
        for (int nt = 0; nt < 8; nt++) {
            float p0 = __expf(s[nt][0] - mn0);
            float p1 = __expf(s[nt][1] - mn0);
            float p2 = __expf(s[nt][2] - mn1);
            float p3 = __expf(s[nt][3] - mn1);
            rs0 += p0 + p1; rs1 += p2 + p3;
            uint2 u0; u0.x = f2tf(p0); u0.y = f2tf(p1);
            uint2 u1; u1.x = f2tf(p2); u1.y = f2tf(p3);
            *(uint2*)&Ps[(q0 + gr) * ATP + nt * 8 + 2 * tig] = u0;
            *(uint2*)&Ps[(q0 + gr + 8) * ATP + nt * 8 + 2 * tig] = u1;
        }
        rs0 += __shfl_xor_sync(0xffffffffu, rs0, 1);
        rs0 += __shfl_xor_sync(0xffffffffu, rs0, 2);
        rs1 += __shfl_xor_sync(0xffffffffu, rs1, 1);
        rs1 += __shfl_xor_sync(0xffffffffu, rs1, 2);
        l0 = l0 * sc0 + rs0; l1 = l1 * sc1 + rs1;
        m0 = mn0; m1 = mn1;
#pragma unroll
        for (int nt = 0; nt < 8; nt++) {
            o[nt][0] *= sc0; o[nt][1] *= sc0;
            o[nt][2] *= sc1; o[nt][3] *= sc1;
        }
        __syncwarp();

        // ---- O += P V ----
#pragma unroll
        for (int kk = 0; kk < 8; kk++) {
            unsigned af[4];
            int o0i = (q0 + gr) * ATP + kk * 8 + tig;
            int o1i = (q0 + gr + 8) * ATP + kk * 8 + tig;
            af[0] = Ps[o0i];     af[1] = Ps[o1i];
            af[2] = Ps[o0i + 4]; af[3] = Ps[o1i + 4];
#pragma unroll
            for (int nt2 = 0; nt2 < 8; nt2++) {
                int ob = (nt2 * 8 + gr) * ATP + kk * 8 + tig;
                mma8(o[nt2], af, Vt[ob], Vt[ob + 4]);
            }
        }
    }

    float inv0 = 1.f / l0, inv1 = 1.f / l1;
    size_t r0 = (size_t)(b * S + qt * 64 + q0 + gr) * D_ + h * 64;
    size_t r1 = r0 + 8 * D_;
#pragma unroll
    for (int nt2 = 0; nt2 < 8; nt2++) {
        int col = nt2 * 8 + 2 * tig;
        ctx[r0 + col]     = o[nt2][0] * inv0;
        ctx[r0 + col + 1] = o[nt2][1] * inv0;
        ctx[r1 + col]     = o[nt2][2] * inv1;
        ctx[r1 + col + 1] = o[nt2][3] * inv1;
    }
}

// ---------------- layernorm (in place, D=512) -------------------------------
__global__ __launch_bounds__(128) void ln_k(float* __restrict__ x,
                                            const float* __restrict__ g,
                                            const float* __restrict__ bt)
{
    __shared__ float sm8[8];
    int row = blockIdx.x, tid = threadIdx.x;
    float4* xr = (float4*)(x + (size_t)row * D_);
    float4 v = xr[tid];
    float s = v.x + v.y + v.z + v.w;
#pragma unroll
    for (int o = 16; o; o >>= 1) s += __shfl_xor_sync(0xffffffffu, s, o);
    if ((tid & 31) == 0) sm8[tid >> 5] = s;
    __syncthreads();
    float mean = (sm8[0] + sm8[1] + sm8[2] + sm8[3]) * (1.f / (float)D_);
    float d0 = v.x - mean, d1 = v.y - mean, d2 = v.z - mean, d3 = v.w - mean;
    float q = d0 * d0 + d1 * d1 + d2 * d2 + d3 * d3;
#pragma unroll
    for (int o = 16; o; o >>= 1) q += __shfl_xor_sync(0xffffffffu, q, o);
    if ((tid & 31) == 0) sm8[4 + (tid >> 5)] = q;
    __syncthreads();
    float var = (sm8[4] + sm8[5] + sm8[6] + sm8[7]) * (1.f / (float)D_);
    float inv = rsqrtf(var + 1e-5f);
    float4 g4 = ((const float4*)g)[tid];
    float4 b4 = ((const float4*)bt)[tid];
    v.x = d0 * inv * g4.x + b4.x;
    v.y = d1 * inv * g4.y + b4.y;
    v.z = d2 * inv * g4.z + b4.z;
    v.w = d3 * inv * g4.w + b4.w;
    xr[tid] = v;
}

// ---------------- length regulator ------------------------------------------
__global__ void regidx_k(const int* __restrict__ dur, int* __restrict__ idx)
{
    __shared__ int cums[T_];
    int b = blockIdx.x, tid = threadIdx.x;
    cums[tid] = dur[b * T_ + tid];
    __syncthreads();
    if (tid == 0) {
        int a = 0;
        for (int t = 0; t < T_; t++) { a += cums[t]; cums[t] = a; }
    }
    __syncthreads();
    for (int f = tid; f < MEL_; f += T_) {
        int lo = 0, hi = T_;
        while (lo < hi) {
            int mid = (lo + hi) >> 1;
            if (cums[mid] <= f) lo = mid + 1; else hi = mid;
        }
        idx[b * MEL_ + f] = (lo > T_ - 1) ? (T_ - 1) : lo;
    }
}

__global__ void gather_k(const float* __restrict__ enc, const int* __restrict__ idx,
                         const int* __restrict__ mlen, float* __restrict__ out)
{
    int row = blockIdx.x;            // b*MEL + f
    int b = row >> 10, f = row & 1023;
    float keep = (f <= mlen[b]) ? 1.f : 0.f;
    int t = idx[row];
    int tid = threadIdx.x;
    float4 v = ((const float4*)(enc + (size_t)(b * T_ + t) * D_))[tid];
    v.x *= keep; v.y *= keep; v.z *= keep; v.w *= keep;
    ((float4*)(out + (size_t)row * D_))[tid] = v;
}

// ---------------- per-layer driver ------------------------------------------
template<int SLOG>
static void runLayerT(const float* const* W, int l, float* x, float* y,
                      const int* lens, float* gqkv, float* gctx, float* gh)
{
    const int S = 1 << SLOG;
    const int N = B_ * S;
    const float* wqkv = W[0]  + (size_t)l * D_ * 3 * D_;
    const float* bqkv = W[1]  + (size_t)l * 3 * D_;
    const float* wo   = W[2]  + (size_t)l * D_ * D_;
    const float* bo   = W[3]  + (size_t)l * D_;
    const float* l1g  = W[4]  + (size_t)l * D_;
    const float* l1b  = W[5]  + (size_t)l * D_;
    const float* c1w  = W[6]  + (size_t)l * 3 * D_ * INTER_;
    const float* c1b  = W[7]  + (size_t)l * INTER_;
    const float* c2w  = W[8]  + (size_t)l * 3 * INTER_ * D_;
    const float* c2b  = W[9]  + (size_t)l * D_;
    const float* l2g  = W[10] + (size_t)l * D_;
    const float* l2b  = W[11] + (size_t)l * D_;

    gemm_tc<0, 0, 0, false, false, false><<<dim3(12, N / 128), 256>>>(
        x, wqkv, bqkv, nullptr, gqkv, N, 3 * D_, D_);
    attn_tc<<<dim3(S / 64, B_ * H_), 128, ATTN_SMEM>>>(gqkv, lens, gctx, S);
    gemm_tc<0, 0, 0, false, true, false><<<dim3(4, N / 128), 256>>>(
        gctx, wo, bo, x, y, N, D_, D_);
    ln_k<<<N, 128>>>(y, l1g, l1b);
    gemm_tc<1, SLOG, 9, true, false, false><<<dim3(16, N / 128), 256>>>(
        y, c1w, c1b, nullptr, gh, N, INTER_, 3 * D_);
    gemm_tc<1, SLOG, 11, false, true, false><<<dim3(4, N / 128), 256>>>(
        gh, c2w, c2b, y, x, N, D_, 3 * INTER_);
    ln_k<<<N, 128>>>(x, l2g, l2b);
}

// ---------------- driver -----------------------------------------------------
extern "C" void kernel_launch(void* const* d_in, const int* in_sizes, int n_in,
                              void* d_out, int out_size)
{
    const int* tokens = (const int*)d_in[0];
    const int* tlen   = (const int*)d_in[1];
    const int* mlen   = (const int*)d_in[2];
    const int* dur    = (const int*)d_in[3];

    int ei = n_in - 27;
    if (ei < 0 || in_sizes[ei] != 256 * D_) {
        for (int i = 0; i < n_in; i++)
            if (in_sizes[i] == 256 * D_) { ei = i; break; }
    }
    const float* emb = (const float*)d_in[ei];
    const float* P[26];
    for (int i = 0; i < 26; i++) P[i] = (const float*)d_in[ei + 1 + i];

    float *gx, *gy, *gctx, *gqkv, *gh;
    int* gidx;
    cudaGetSymbolAddress((void**)&gx,   g_x);
    cudaGetSymbolAddress((void**)&gy,   g_y);
    cudaGetSymbolAddress((void**)&gctx, g_ctx);
    cudaGetSymbolAddress((void**)&gqkv, g_qkv);
    cudaGetSymbolAddress((void**)&gh,   g_h);
    cudaGetSymbolAddress((void**)&gidx, g_idx);

    cudaFuncSetAttribute(attn_tc, cudaFuncAttributeMaxDynamicSharedMemorySize,
                         ATTN_SMEM);

    embed_k<<<B_ * T_, 128>>>(tokens, emb, gx);

    for (int l = 0; l < L_; l++)
        runLayerT<8>(P, l, gx, gy, tlen, gqkv, gctx, gh);

    regidx_k<<<B_, T_>>>(dur, gidx);
    gather_k<<<B_ * MEL_, 128>>>(gx, gidx, mlen, gy);

    for (int l = 0; l < L_; l++)
        runLayerT<10>(P + 12, l, gy, gx, mlen, gqkv, gctx, gh);

    gemm_tc<0, 0, 0, false, false, true><<<dim3(1, (B_ * MEL_) / 128), 256>>>(
        gy, P[24], P[25], nullptr, (float*)d_out, B_ * MEL_, OUT_, D_);
}

// round 9
// speedup vs baseline: 2.1911x; 1.1071x over previous
#include <cuda_runtime.h>
#include <cstdint>

#define B_    16
#define T_    256
#define MEL_  1024
#define D_    512
#define H_    8
#define L_    4
#define INTER_ 2048
#define OUT_  80

// ---------------- scratch (static device globals: no allocations) ----------
__device__ float g_x  [(size_t)B_*MEL_*D_];
__device__ float g_y  [(size_t)B_*MEL_*D_];
__device__ float g_ctx[(size_t)B_*MEL_*D_];
__device__ float g_qkv[(size_t)B_*MEL_*3*D_];
__device__ float g_h  [(size_t)B_*MEL_*INTER_];
__device__ int   g_idx[B_*MEL_];

__device__ __forceinline__ unsigned f2tf(float x)
{
    unsigned u;
    asm("cvt.rna.tf32.f32 %0, %1;" : "=r"(u) : "f"(x));
    return u;
}

__device__ __forceinline__ void mma8(float* c, const unsigned* a,
                                     unsigned b0, unsigned b1)
{
    asm volatile(
        "mma.sync.aligned.m16n8k8.row.col.f32.tf32.tf32.f32 "
        "{%0,%1,%2,%3}, {%4,%5,%6,%7}, {%8,%9}, {%0,%1,%2,%3};"
        : "+f"(c[0]), "+f"(c[1]), "+f"(c[2]), "+f"(c[3])
        : "r"(a[0]), "r"(a[1]), "r"(a[2]), "r"(a[3]), "r"(b0), "r"(b1));
}

// ---------------- embedding + positional encoding --------------------------
__global__ void embed_k(const int* __restrict__ tokens,
                        const float* __restrict__ emb,
                        float* __restrict__ x)
{
    int row = blockIdx.x;            // b*T + t
    int b   = row >> 8;              // T_=256
    int tok = tokens[row];
    int tid = threadIdx.x;           // 128 threads, float4 each
    float4 e = ((const float4*)(emb + (size_t)tok * D_))[tid];
    int d0 = tid * 4;
    const float c = 9.210340371976184f / (float)D_;   // ln(10000)/D
    float den0 = __expf(-(float)(d0)     * c);
    float den1 = __expf(-(float)(d0 + 2) * c);
    float a0 = (float)b * den0, a1 = (float)b * den1;
    float4 o;
    o.x = 2.f * e.x + sinf(a0);
    o.y = 2.f * e.y + cosf(a0);
    o.z = 2.f * e.z + sinf(a1);
    o.w = 2.f * e.w + cosf(a1);
    ((float4*)(x + (size_t)row * D_))[tid] = o;
}

// ---------------- TF32 tensor-core GEMM  C = op(A) @ W + bias (+R) ---------
// 128x128 CTA tile, BK=16, 8 warps each 32x64, m16n8k8 tf32 HMMA.
// __launch_bounds__(256, 2): cap regs at 128 -> 2 CTAs/SM (occupancy fix;
// R6 profile showed regs=140 -> 1 CTA/SM -> issue 22%).
// CONV==1: A is [B*S, Din], virtual K = 3*Din, SAME zero padding.
//          S = 1<<SLOG, Din = 1<<DLOG (all shifts, no division).
// TRANS==1: store C[row,col] at out[(b*OUT_+col)*MEL_ + f]  (row = b*MEL_+f)
#define APIT 20
#define BPIT 136

template<int CONV, int SLOG, int DLOG, bool RELU, bool RESID, bool TRANS>
__global__ __launch_bounds__(256, 2) void gemm_tc(
    const float* __restrict__ A, const float* __restrict__ W,
    const float* __restrict__ bias, const float* __restrict__ R,
    float* __restrict__ C, int N, int M, int Kd)
{
    __shared__ unsigned As[2][128 * APIT];
    __shared__ unsigned Bs[2][16 * BPIT];

    int tid  = threadIdx.x;
    int lane = tid & 31, warp = tid >> 5;
    int wm = warp & 3, wn = warp >> 2;        // warp tile: rows wm*32, cols wn*64
    int gr = lane >> 2, tig = lane & 3;
    int rowB = blockIdx.y * 128, colB = blockIdx.x * 128;

    // per-thread A-load geometry (constant across K-loop)
    int akb = (tid & 3) * 4;                  // k-sub offset 0..12
    int rr0 = rowB + (tid >> 2);              // row for i=0
    int rr1 = rr0 + 64;                       // row for i=1
    bool lo0 = true, hi0 = true, lo1 = true, hi1 = true;
    if (CONV) {
        int SM1 = (1 << SLOG) - 1;
        int ss0 = rr0 & SM1, ss1 = rr1 & SM1;
        lo0 = ss0 > 0;  hi0 = ss0 < SM1;
        lo1 = ss1 > 0;  hi1 = ss1 < SM1;
    }
    // per-thread B-load geometry
    int bkt = tid >> 5;                       // 0..7 (two i-steps add +8)
    int bc  = (tid & 31) * 4;
    int bcol = colB + bc;

    float acc[2][8][4];
#pragma unroll
    for (int i = 0; i < 2; i++)
#pragma unroll
        for (int j = 0; j < 8; j++)
#pragma unroll
            for (int q = 0; q < 4; q++) acc[i][j][q] = 0.f;

    float4 aS[2], bS[2];

    auto ldgA = [&](int k0) {
        int kk = k0 + akb;
        if (CONV == 0) {
            aS[0] = *(const float4*)(A + (size_t)rr0 * Kd + kk);
            aS[1] = *(const float4*)(A + (size_t)rr1 * Kd + kk);
        } else {
            int kc = kk >> DLOG;
            int dd = kk & ((1 << DLOG) - 1);
            bool ok0 = (kc == 1) || (kc == 0 ? lo0 : hi0);
            bool ok1 = (kc == 1) || (kc == 0 ? lo1 : hi1);
            const float* p = A + ((size_t)(kc - 1) << DLOG) + dd;
            float4 z = make_float4(0.f, 0.f, 0.f, 0.f);
            aS[0] = ok0 ? *(const float4*)(p + ((size_t)rr0 << DLOG)) : z;
            aS[1] = ok1 ? *(const float4*)(p + ((size_t)rr1 << DLOG)) : z;
        }
    };
    auto ldgB = [&](int k0) {
        float4 z = make_float4(0.f, 0.f, 0.f, 0.f);
        bS[0] = (bcol < M) ? *(const float4*)(W + (size_t)(k0 + bkt) * M + bcol) : z;
        bS[1] = (bcol < M) ? *(const float4*)(W + (size_t)(k0 + bkt + 8) * M + bcol) : z;
    };
    auto sts = [&](int s) {
        int r = tid >> 2;
#pragma unroll
        for (int i = 0; i < 2; i++) {
            uint4 ta;
            ta.x = f2tf(aS[i].x); ta.y = f2tf(aS[i].y);
            ta.z = f2tf(aS[i].z); ta.w = f2tf(aS[i].w);
            *(uint4*)&As[s][(r + i * 64) * APIT + akb] = ta;
            uint4 tb;
            tb.x = f2tf(bS[i].x); tb.y = f2tf(bS[i].y);
            tb.z = f2tf(bS[i].z); tb.w = f2tf(bS[i].w);
            *(uint4*)&Bs[s][(bkt + i * 8) * BPIT + bc] = tb;
        }
    };
    auto compute = [&](int s) {
#pragma unroll
        for (int ks = 0; ks < 2; ks++) {
            int kb = ks * 8;
            unsigned af[2][4], bf[8][2];
#pragma unroll
            for (int mi = 0; mi < 2; mi++) {
                int m = wm * 32 + mi * 16 + gr;
                af[mi][0] = As[s][m * APIT + kb + tig];
                af[mi][1] = As[s][(m + 8) * APIT + kb + tig];
                af[mi][2] = As[s][m * APIT + kb + tig + 4];
                af[mi][3] = As[s][(m + 8) * APIT + kb + tig + 4];
            }
#pragma unroll
            for (int ni = 0; ni < 8; ni++) {
                int n = wn * 64 + ni * 8 + gr;
                bf[ni][0] = Bs[s][(kb + tig) * BPIT + n];
                bf[ni][1] = Bs[s][(kb + tig + 4) * BPIT + n];
            }
#pragma unroll
            for (int mi = 0; mi < 2; mi++)
#pragma unroll
                for (int ni = 0; ni < 8; ni++)
                    mma8(acc[mi][ni], af[mi], bf[ni][0], bf[ni][1]);
        }
    };

    ldgA(0); ldgB(0);
    int s = 0;
    for (int k0 = 0; k0 < Kd; k0 += 16) {
        sts(s);
        __syncthreads();
        if (k0 + 16 < Kd) { ldgA(k0 + 16); ldgB(k0 + 16); }
        compute(s);
        s ^= 1;
    }

#pragma unroll
    for (int mi = 0; mi < 2; mi++) {
        int r0 = rowB + wm * 32 + mi * 16 + gr;
#pragma unroll
        for (int ni = 0; ni < 8; ni++) {
            int c0 = colB + wn * 64 + ni * 8 + tig * 2;
#pragma unroll
            for (int hh = 0; hh < 2; hh++) {
                int r = r0 + hh * 8;
#pragma unroll
                for (int cc = 0; cc < 2; cc++) {
                    int col = c0 + cc;
                    if (col >= M) continue;
                    float v = acc[mi][ni][hh * 2 + cc] + bias[col];
                    if (RESID) v += R[(size_t)r * M + col];
                    if (RELU)  v = fmaxf(v, 0.f);
                    if (!TRANS) {
                        C[(size_t)r * M + col] = v;
                    } else {
                        int bb = r >> 10, f = r & 1023;
                        C[((size_t)(bb * OUT_ + col)) * MEL_ + f] = v;
                    }
                }
            }
        }
    }
}

// ---------------- tensor-core flash attention (tf32) -----------------------
// 4 warps, 64 q rows per CTA (16 per warp), kv chunks of 64.
#define ATP 68
#define ATTN_SMEM (3 * 64 * ATP * 4)
__global__ __launch_bounds__(128) void attn_tc(const float* __restrict__ qkv,
                                               const int* __restrict__ lens,
                                               float* __restrict__ ctx, int S)
{
    extern __shared__ unsigned asmm[];
    unsigned* Ps = asmm;              // Q tile first, then reused for P
    unsigned* Ks = Ps + 64 * ATP;
    unsigned* Vt = Ks + 64 * ATP;

    int tid  = threadIdx.x;
    int lane = tid & 31, warp = tid >> 5;
    int gr = lane >> 2, tig = lane & 3;
    int b = blockIdx.y >> 3, h = blockIdx.y & 7;
    int qt = blockIdx.x;
    int len = lens[b];
    const float* base = qkv + (size_t)b * S * (3 * D_);

    // ---- load Q tile (scaled by 1/8, tf32) ----
#pragma unroll
    for (int i = 0; i < 8; i++) {
        int idx = i * 128 + tid;
        int tok = idx >> 4, d4 = (idx & 15) * 4;
        float4 q = *(const float4*)(base + (size_t)(qt * 64 + tok) * (3 * D_)
                                    + h * 64 + d4);
        uint4 t;
        t.x = f2tf(q.x * 0.125f); t.y = f2tf(q.y * 0.125f);
        t.z = f2tf(q.z * 0.125f); t.w = f2tf(q.w * 0.125f);
        *(uint4*)&Ps[tok * ATP + d4] = t;
    }
    __syncthreads();

    int q0 = warp * 16;
    unsigned qf[8][4];
#pragma unroll
    for (int kk = 0; kk < 8; kk++) {
        int o0 = (q0 + gr) * ATP + kk * 8 + tig;
        int o1 = (q0 + gr + 8) * ATP + kk * 8 + tig;
        qf[kk][0] = Ps[o0];     qf[kk][1] = Ps[o1];
        qf[kk][2] = Ps[o0 + 4]; qf[kk][3] = Ps[o1 + 4];
    }

    float m0 = -3.0e38f, m1 = -3.0e38f, l0 = 0.f, l1 = 0.f;
    float o[8][4];
#pragma unroll
    for (int i = 0; i < 8; i++)
#pragma unroll
        for (int j = 0; j < 4; j++) o[i][j] = 0.f;

    // keys with kg > len are masked out -> only iterate tiles that intersect
    int nkt = S >> 6;
    int need = (len >> 6) + 1;
    if (need < nkt) nkt = need;

    for (int kt = 0; kt < nkt; kt++) {
        __syncthreads();
        // K tile: row-major [tok][d]
#pragma unroll
        for (int i = 0; i < 8; i++) {
            int idx = i * 128 + tid;
            int tok = idx >> 4, d4 = (idx & 15) * 4;
            float4 k = *(const float4*)(base
                + (size_t)(kt * 64 + tok) * (3 * D_) + D_ + h * 64 + d4);
            uint4 t;
            t.x = f2tf(k.x); t.y = f2tf(k.y); t.z = f2tf(k.z); t.w = f2tf(k.w);
            *(uint4*)&Ks[tok * ATP + d4] = t;
        }
        // V tile transposed: Vt[d][tok]
        {
            int d = tid & 63, tq0 = tid >> 6;
#pragma unroll
            for (int i = 0; i < 8; i++) {
                int tok = (tq0 * 8 + i) * 4;
                const float* vb = base + (size_t)(kt * 64 + tok) * (3 * D_)
                                  + 2 * D_ + h * 64 + d;
                uint4 t;
                t.x = f2tf(vb[0]);
                t.y = f2tf(vb[3 * D_]);
                t.z = f2tf(vb[6 * D_]);
                t.w = f2tf(vb[9 * D_]);
                *(uint4*)&Vt[d * ATP + tok] = t;
            }
        }
        __syncthreads();

        // ---- S = Q K^T ----
        float s[8][4];
#pragma unroll
        for (int nt = 0; nt < 8; nt++)
#pragma unroll
            for (int j = 0; j < 4; j++) s[nt][j] = 0.f;
#pragma unroll
        for (int kk = 0; kk < 8; kk++)
#pragma unroll
            for (int nt = 0; nt < 8; nt++) {
                int ob = (nt * 8 + gr) * ATP + kk * 8 + tig;
                mma8(s[nt], qf[kk], Ks[ob], Ks[ob + 4]);
            }

        // ---- mask + online softmax ----
        float mx0 = -3.0e38f, mx1 = -3.0e38f;
#pragma unroll
        for (int nt = 0; nt < 8; nt++) {
            int c0 = kt * 64 + nt * 8 + 2 * tig;
            if (c0 > len)     { s[nt][0] = -1.0e30f; s[nt][2] = -1.0e30f; }
            if (c0 + 1 > len) { s[nt][1] = -1.0e30f; s[nt][3] = -1.0e30f; }
            mx0 = fmaxf(mx0, fmaxf(s[nt][0], s[nt][1]));
            mx1 = fmaxf(mx1, fmaxf(s[nt][2], s[nt][3]));
        }
        mx0 = fmaxf(mx0, __shfl_xor_sync(0xffffffffu, mx0, 1));
        mx0 = fmaxf(mx0, __shfl_xor_sync(0xffffffffu, mx0, 2));
        mx1 = fmaxf(mx1, __shfl_xor_sync(0xffffffffu, mx1, 1));
        mx1 = fmaxf(mx1, __shfl_xor_sync(0xffffffffu, mx1, 2));
        float mn0 = fmaxf(m0, mx0), mn1 = fmaxf(m1, mx1);
        float sc0 = __expf(m0 - mn0), sc1 = __expf(m1 - mn1);
        float rs0 = 0.f, rs1 = 0.f;
#pragma unroll
        for (int nt = 0; nt < 8; nt++) {
            float p0 = __expf(s[nt][0] - mn0);
            float p1 = __expf(s[nt][1] - mn0);
            float p2 = __expf(s[nt][2] - mn1);
            float p3 = __expf(s[nt][3] - mn1);
            rs0 += p0 + p1; rs1 += p2 + p3;
            uint2 u0; u0.x = f2tf(p0); u0.y = f2tf(p1);
            uint2 u1; u1.x = f2tf(p2); u1.y = f2tf(p3);
            *(uint2*)&Ps[(q0 + gr) * ATP + nt * 8 + 2 * tig] = u0;
            *(uint2*)&Ps[(q0 + gr + 8) * ATP + nt * 8 + 2 * tig] = u1;
        }
        rs0 += __shfl_xor_sync(0xffffffffu, rs0, 1);
        rs0 += __shfl_xor_sync(0xffffffffu, rs0, 2);
        rs1 += __shfl_xor_sync(0xffffffffu, rs1, 1);
        rs1 += __shfl_xor_sync(0xffffffffu, rs1, 2);
        l0 = l0 * sc0 + rs0; l1 = l1 * sc1 + rs1;
        m0 = mn0; m1 = mn1;
#pragma unroll
        for (int nt = 0; nt < 8; nt++) {
            o[nt][0] *= sc0; o[nt][1] *= sc0;
            o[nt][2] *= sc1; o[nt][3] *= sc1;
        }
        __syncwarp();

        // ---- O += P V ----
#pragma unroll
        for (int kk = 0; kk < 8; kk++) {
            unsigned af[4];
            int o0i = (q0 + gr) * ATP + kk * 8 + tig;
            int o1i = (q0 + gr + 8) * ATP + kk * 8 + tig;
            af[0] = Ps[o0i];     af[1] = Ps[o1i];
            af[2] = Ps[o0i + 4]; af[3] = Ps[o1i + 4];
#pragma unroll
            for (int nt2 = 0; nt2 < 8; nt2++) {
                int ob = (nt2 * 8 + gr) * ATP + kk * 8 + tig;
                mma8(o[nt2], af, Vt[ob], Vt[ob + 4]);
            }
        }
    }

    float inv0 = 1.f / l0, inv1 = 1.f / l1;
    size_t r0 = (size_t)(b * S + qt * 64 + q0 + gr) * D_ + h * 64;
    size_t r1 = r0 + 8 * D_;
#pragma unroll
    for (int nt2 = 0; nt2 < 8; nt2++) {
        int col = nt2 * 8 + 2 * tig;
        ctx[r0 + col]     = o[nt2][0] * inv0;
        ctx[r0 + col + 1] = o[nt2][1] * inv0;
        ctx[r1 + col]     = o[nt2][2] * inv1;
        ctx[r1 + col + 1] = o[nt2][3] * inv1;
    }
}

// ---------------- layernorm (in place, D=512) -------------------------------
__global__ __launch_bounds__(128) void ln_k(float* __restrict__ x,
                                            const float* __restrict__ g,
                                            const float* __restrict__ bt)
{
    __shared__ float sm8[8];
    int row = blockIdx.x, tid = threadIdx.x;
    float4* xr = (float4*)(x + (size_t)row * D_);
    float4 v = xr[tid];
    float s = v.x + v.y + v.z + v.w;
#pragma unroll
    for (int o = 16; o; o >>= 1) s += __shfl_xor_sync(0xffffffffu, s, o);
    if ((tid & 31) == 0) sm8[tid >> 5] = s;
    __syncthreads();
    float mean = (sm8[0] + sm8[1] + sm8[2] + sm8[3]) * (1.f / (float)D_);
    float d0 = v.x - mean, d1 = v.y - mean, d2 = v.z - mean, d3 = v.w - mean;
    float q = d0 * d0 + d1 * d1 + d2 * d2 + d3 * d3;
#pragma unroll
    for (int o = 16; o; o >>= 1) q += __shfl_xor_sync(0xffffffffu, q, o);
    if ((tid & 31) == 0) sm8[4 + (tid >> 5)] = q;
    __syncthreads();
    float var = (sm8[4] + sm8[5] + sm8[6] + sm8[7]) * (1.f / (float)D_);
    float inv = rsqrtf(var + 1e-5f);
    float4 g4 = ((const float4*)g)[tid];
    float4 b4 = ((const float4*)bt)[tid];
    v.x = d0 * inv * g4.x + b4.x;
    v.y = d1 * inv * g4.y + b4.y;
    v.z = d2 * inv * g4.z + b4.z;
    v.w = d3 * inv * g4.w + b4.w;
    xr[tid] = v;
}

// ---------------- length regulator ------------------------------------------
__global__ void regidx_k(const int* __restrict__ dur, int* __restrict__ idx)
{
    __shared__ int cums[T_];
    int b = blockIdx.x, tid = threadIdx.x;
    cums[tid] = dur[b * T_ + tid];
    __syncthreads();
    if (tid == 0) {
        int a = 0;
        for (int t = 0; t < T_; t++) { a += cums[t]; cums[t] = a; }
    }
    __syncthreads();
    for (int f = tid; f < MEL_; f += T_) {
        int lo = 0, hi = T_;
        while (lo < hi) {
            int mid = (lo + hi) >> 1;
            if (cums[mid] <= f) lo = mid + 1; else hi = mid;
        }
        idx[b * MEL_ + f] = (lo > T_ - 1) ? (T_ - 1) : lo;
    }
}

__global__ void gather_k(const float* __restrict__ enc, const int* __restrict__ idx,
                         const int* __restrict__ mlen, float* __restrict__ out)
{
    int row = blockIdx.x;            // b*MEL + f
    int b = row >> 10, f = row & 1023;
    float keep = (f <= mlen[b]) ? 1.f : 0.f;
    int t = idx[row];
    int tid = threadIdx.x;
    float4 v = ((const float4*)(enc + (size_t)(b * T_ + t) * D_))[tid];
    v.x *= keep; v.y *= keep; v.z *= keep; v.w *= keep;
    ((float4*)(out + (size_t)row * D_))[tid] = v;
}

// ---------------- per-layer driver ------------------------------------------
template<int SLOG>
static void runLayerT(const float* const* W, int l, float* x, float* y,
                      const int* lens, float* gqkv, float* gctx, float* gh)
{
    const int S = 1 << SLOG;
    const int N = B_ * S;
    const float* wqkv = W[0]  + (size_t)l * D_ * 3 * D_;
    const float* bqkv = W[1]  + (size_t)l * 3 * D_;
    const float* wo   = W[2]  + (size_t)l * D_ * D_;
    const float* bo   = W[3]  + (size_t)l * D_;
    const float* l1g  = W[4]  + (size_t)l * D_;
    const float* l1b  = W[5]  + (size_t)l * D_;
    const float* c1w  = W[6]  + (size_t)l * 3 * D_ * INTER_;
    const float* c1b  = W[7]  + (size_t)l * INTER_;
    const float* c2w  = W[8]  + (size_t)l * 3 * INTER_ * D_;
    const float* c2b  = W[9]  + (size_t)l * D_;
    const float* l2g  = W[10] + (size_t)l * D_;
    const float* l2b  = W[11] + (size_t)l * D_;

    gemm_tc<0, 0, 0, false, false, false><<<dim3(12, N / 128), 256>>>(
        x, wqkv, bqkv, nullptr, gqkv, N, 3 * D_, D_);
    attn_tc<<<dim3(S / 64, B_ * H_), 128, ATTN_SMEM>>>(gqkv, lens, gctx, S);
    gemm_tc<0, 0, 0, false, true, false><<<dim3(4, N / 128), 256>>>(
        gctx, wo, bo, x, y, N, D_, D_);
    ln_k<<<N, 128>>>(y, l1g, l1b);
    gemm_tc<1, SLOG, 9, true, false, false><<<dim3(16, N / 128), 256>>>(
        y, c1w, c1b, nullptr, gh, N, INTER_, 3 * D_);
    gemm_tc<1, SLOG, 11, false, true, false><<<dim3(4, N / 128), 256>>>(
        gh, c2w, c2b, y, x, N, D_, 3 * INTER_);
    ln_k<<<N, 128>>>(x, l2g, l2b);
}

// ---------------- driver -----------------------------------------------------
extern "C" void kernel_launch(void* const* d_in, const int* in_sizes, int n_in,
                              void* d_out, int out_size)
{
    const int* tokens = (const int*)d_in[0];
    const int* tlen   = (const int*)d_in[1];
    const int* mlen   = (const int*)d_in[2];
    const int* dur    = (const int*)d_in[3];

    int ei = n_in - 27;
    if (ei < 0 || in_sizes[ei] != 256 * D_) {
        for (int i = 0; i < n_in; i++)
            if (in_sizes[i] == 256 * D_) { ei = i; break; }
    }
    const float* emb = (const float*)d_in[ei];
    const float* P[26];
    for (int i = 0; i < 26; i++) P[i] = (const float*)d_in[ei + 1 + i];

    float *gx, *gy, *gctx, *gqkv, *gh;
    int* gidx;
    cudaGetSymbolAddress((void**)&gx,   g_x);
    cudaGetSymbolAddress((void**)&gy,   g_y);
    cudaGetSymbolAddress((void**)&gctx, g_ctx);
    cudaGetSymbolAddress((void**)&gqkv, g_qkv);
    cudaGetSymbolAddress((void**)&gh,   g_h);
    cudaGetSymbolAddress((void**)&gidx, g_idx);

    cudaFuncSetAttribute(attn_tc, cudaFuncAttributeMaxDynamicSharedMemorySize,
                         ATTN_SMEM);

    embed_k<<<B_ * T_, 128>>>(tokens, emb, gx);

    for (int l = 0; l < L_; l++)
        runLayerT<8>(P, l, gx, gy, tlen, gqkv, gctx, gh);

    regidx_k<<<B_, T_>>>(dur, gidx);
    gather_k<<<B_ * MEL_, 128>>>(gx, gidx, mlen, gy);

    for (int l = 0; l < L_; l++)
        runLayerT<10>(P + 12, l, gy, gx, mlen, gqkv, gctx, gh);

    gemm_tc<0, 0, 0, false, false, true><<<dim3(1, (B_ * MEL_) / 128), 256>>>(
        gy, P[24], P[25], nullptr, (float*)d_out, B_ * MEL_, OUT_, D_);
}

// round 10
// speedup vs baseline: 2.2348x; 1.0199x over previous
#include <cuda_runtime.h>
#include <cstdint>

#define B_    16
#define T_    256
#define MEL_  1024
#define D_    512
#define H_    8
#define L_    4
#define INTER_ 2048
#define OUT_  80

// ---------------- scratch (static device globals: no allocations) ----------
__device__ float g_x  [(size_t)B_*MEL_*D_];
__device__ float g_y  [(size_t)B_*MEL_*D_];
__device__ float g_ctx[(size_t)B_*MEL_*D_];
__device__ float g_qkv[(size_t)B_*MEL_*3*D_];
__device__ float g_h  [(size_t)B_*MEL_*INTER_];
__device__ int   g_idx[B_*MEL_];

__device__ __forceinline__ unsigned f2tf(float x)
{
    unsigned u;
    asm("cvt.rna.tf32.f32 %0, %1;" : "=r"(u) : "f"(x));
    return u;
}

__device__ __forceinline__ void mma8(float* c, const unsigned* a,
                                     unsigned b0, unsigned b1)
{
    asm volatile(
        "mma.sync.aligned.m16n8k8.row.col.f32.tf32.tf32.f32 "
        "{%0,%1,%2,%3}, {%4,%5,%6,%7}, {%8,%9}, {%0,%1,%2,%3};"
        : "+f"(c[0]), "+f"(c[1]), "+f"(c[2]), "+f"(c[3])
        : "r"(a[0]), "r"(a[1]), "r"(a[2]), "r"(a[3]), "r"(b0), "r"(b1));
}

// ---------------- embedding + positional encoding --------------------------
__global__ void embed_k(const int* __restrict__ tokens,
                        const float* __restrict__ emb,
                        float* __restrict__ x)
{
    int row = blockIdx.x;            // b*T + t
    int b   = row >> 8;              // T_=256
    int tok = tokens[row];
    int tid = threadIdx.x;           // 128 threads, float4 each
    float4 e = ((const float4*)(emb + (size_t)tok * D_))[tid];
    int d0 = tid * 4;
    const float c = 9.210340371976184f / (float)D_;   // ln(10000)/D
    float den0 = __expf(-(float)(d0)     * c);
    float den1 = __expf(-(float)(d0 + 2) * c);
    float a0 = (float)b * den0, a1 = (float)b * den1;
    float4 o;
    o.x = 2.f * e.x + sinf(a0);
    o.y = 2.f * e.y + cosf(a0);
    o.z = 2.f * e.z + sinf(a1);
    o.w = 2.f * e.w + cosf(a1);
    ((float4*)(x + (size_t)row * D_))[tid] = o;
}

// ---------------- TF32 tensor-core GEMM  C = op(A) @ W + bias (+R) ---------
// 128x128 CTA tile, BK=16, **4 warps each 64x64** (128 threads).
// Rationale (R9 profile): kernel is smem-crossbar-byte-bound (L1 41.5%,
// tensor 20%); 64x64 warp tiles cut smem reads from 192B/MMA to 128B/MMA.
// 2 CTAs/SM at ~200 regs x 128 thr keeps 8 warps/SM.
// CONV==1: A is [B*S, Din], virtual K = 3*Din, SAME zero padding.
//          S = 1<<SLOG, Din = 1<<DLOG (all shifts, no division).
// TRANS==1: store C[row,col] at out[(b*OUT_+col)*MEL_ + f]  (row = b*MEL_+f)
#define APIT 20
#define BPIT 136

template<int CONV, int SLOG, int DLOG, bool RELU, bool RESID, bool TRANS>
__global__ __launch_bounds__(128) void gemm_tc(
    const float* __restrict__ A, const float* __restrict__ W,
    const float* __restrict__ bias, const float* __restrict__ R,
    float* __restrict__ C, int N, int M, int Kd)
{
    __shared__ unsigned As[2][128 * APIT];
    __shared__ unsigned Bs[2][16 * BPIT];

    int tid  = threadIdx.x;
    int lane = tid & 31, warp = tid >> 5;     // 4 warps
    int wm = warp & 1, wn = warp >> 1;        // warp tile: rows wm*64, cols wn*64
    int gr = lane >> 2, tig = lane & 3;
    int rowB = blockIdx.y * 128, colB = blockIdx.x * 128;

    // per-thread A-load geometry: 4 i-steps, row = rowB + (tid>>2) + i*32
    int akb = (tid & 3) * 4;                  // k-sub offset 0..12
    int arl = tid >> 2;                       // 0..31
    bool lo[4], hi[4];
#pragma unroll
    for (int i = 0; i < 4; i++) { lo[i] = true; hi[i] = true; }
    if (CONV) {
        int SM1 = (1 << SLOG) - 1;
#pragma unroll
        for (int i = 0; i < 4; i++) {
            int ss = (rowB + arl + i * 32) & SM1;
            lo[i] = ss > 0;  hi[i] = ss < SM1;
        }
    }
    // per-thread B-load geometry: 4 i-steps, krow = (tid>>5) + i*4
    int bkt = tid >> 5;                       // 0..3
    int bc  = (tid & 31) * 4;
    int bcol = colB + bc;

    float acc[4][8][4];
#pragma unroll
    for (int i = 0; i < 4; i++)
#pragma unroll
        for (int j = 0; j < 8; j++)
#pragma unroll
            for (int q = 0; q < 4; q++) acc[i][j][q] = 0.f;

    float4 aS[4], bS[4];

    auto ldgA = [&](int k0) {
        int kk = k0 + akb;
        if (CONV == 0) {
#pragma unroll
            for (int i = 0; i < 4; i++)
                aS[i] = *(const float4*)(A + (size_t)(rowB + arl + i * 32) * Kd + kk);
        } else {
            int kc = kk >> DLOG;
            int dd = kk & ((1 << DLOG) - 1);
            const float* p = A + ((size_t)(kc - 1) << DLOG) + dd;
            float4 z = make_float4(0.f, 0.f, 0.f, 0.f);
#pragma unroll
            for (int i = 0; i < 4; i++) {
                bool ok = (kc == 1) || (kc == 0 ? lo[i] : hi[i]);
                int r = rowB + arl + i * 32;
                aS[i] = ok ? *(const float4*)(p + ((size_t)r << DLOG)) : z;
            }
        }
    };
    auto ldgB = [&](int k0) {
        float4 z = make_float4(0.f, 0.f, 0.f, 0.f);
#pragma unroll
        for (int i = 0; i < 4; i++)
            bS[i] = (bcol < M)
                ? *(const float4*)(W + (size_t)(k0 + bkt + i * 4) * M + bcol) : z;
    };
    auto sts = [&](int s) {
#pragma unroll
        for (int i = 0; i < 4; i++) {
            uint4 ta;
            ta.x = f2tf(aS[i].x); ta.y = f2tf(aS[i].y);
            ta.z = f2tf(aS[i].z); ta.w = f2tf(aS[i].w);
            *(uint4*)&As[s][(arl + i * 32) * APIT + akb] = ta;
            uint4 tb;
            tb.x = f2tf(bS[i].x); tb.y = f2tf(bS[i].y);
            tb.z = f2tf(bS[i].z); tb.w = f2tf(bS[i].w);
            *(uint4*)&Bs[s][(bkt + i * 4) * BPIT + bc] = tb;
        }
    };
    auto compute = [&](int s) {
#pragma unroll
        for (int ks = 0; ks < 2; ks++) {
            int kb = ks * 8;
            unsigned af[4][4];
#pragma unroll
            for (int mi = 0; mi < 4; mi++) {
                int m = wm * 64 + mi * 16 + gr;
                af[mi][0] = As[s][m * APIT + kb + tig];
                af[mi][1] = As[s][(m + 8) * APIT + kb + tig];
                af[mi][2] = As[s][m * APIT + kb + tig + 4];
                af[mi][3] = As[s][(m + 8) * APIT + kb + tig + 4];
            }
#pragma unroll
            for (int ni = 0; ni < 8; ni++) {
                int n = wn * 64 + ni * 8 + gr;
                unsigned b0 = Bs[s][(kb + tig) * BPIT + n];
                unsigned b1 = Bs[s][(kb + tig + 4) * BPIT + n];
#pragma unroll
                for (int mi = 0; mi < 4; mi++)
                    mma8(acc[mi][ni], af[mi], b0, b1);
            }
        }
    };

    ldgA(0); ldgB(0);
    int s = 0;
    for (int k0 = 0; k0 < Kd; k0 += 16) {
        sts(s);
        __syncthreads();
        if (k0 + 16 < Kd) { ldgA(k0 + 16); ldgB(k0 + 16); }
        compute(s);
        s ^= 1;
    }

#pragma unroll
    for (int mi = 0; mi < 4; mi++) {
        int r0 = rowB + wm * 64 + mi * 16 + gr;
#pragma unroll
        for (int ni = 0; ni < 8; ni++) {
            int c0 = colB + wn * 64 + ni * 8 + tig * 2;
#pragma unroll
            for (int hh = 0; hh < 2; hh++) {
                int r = r0 + hh * 8;
#pragma unroll
                for (int cc = 0; cc < 2; cc++) {
                    int col = c0 + cc;
                    if (col >= M) continue;
                    float v = acc[mi][ni][hh * 2 + cc] + bias[col];
                    if (RESID) v += R[(size_t)r * M + col];
                    if (RELU)  v = fmaxf(v, 0.f);
                    if (!TRANS) {
                        C[(size_t)r * M + col] = v;
                    } else {
                        int bb = r >> 10, f = r & 1023;
                        C[((size_t)(bb * OUT_ + col)) * MEL_ + f] = v;
                    }
                }
            }
        }
    }
}

// ---------------- tensor-core flash attention (tf32) -----------------------
// 4 warps, 64 q rows per CTA (16 per warp), kv chunks of 64.
#define ATP 68
#define ATTN_SMEM (3 * 64 * ATP * 4)
__global__ __launch_bounds__(128) void attn_tc(const float* __restrict__ qkv,
                                               const int* __restrict__ lens,
                                               float* __restrict__ ctx, int S)
{
    extern __shared__ unsigned asmm[];
    unsigned* Ps = asmm;              // Q tile first, then reused for P
    unsigned* Ks = Ps + 64 * ATP;
    unsigned* Vt = Ks + 64 * ATP;

    int tid  = threadIdx.x;
    int lane = tid & 31, warp = tid >> 5;
    int gr = lane >> 2, tig = lane & 3;
    int b = blockIdx.y >> 3, h = blockIdx.y & 7;
    int qt = blockIdx.x;
    int len = lens[b];
    const float* base = qkv + (size_t)b * S * (3 * D_);

    // ---- load Q tile (scaled by 1/8, tf32) ----
#pragma unroll
    for (int i = 0; i < 8; i++) {
        int idx = i * 128 + tid;
        int tok = idx >> 4, d4 = (idx & 15) * 4;
        float4 q = *(const float4*)(base + (size_t)(qt * 64 + tok) * (3 * D_)
                                    + h * 64 + d4);
        uint4 t;
        t.x = f2tf(q.x * 0.125f); t.y = f2tf(q.y * 0.125f);
        t.z = f2tf(q.z * 0.125f); t.w = f2tf(q.w * 0.125f);
        *(uint4*)&Ps[tok * ATP + d4] = t;
    }
    __syncthreads();

    int q0 = warp * 16;
    unsigned qf[8][4];
#pragma unroll
    for (int kk = 0; kk < 8; kk++) {
        int o0 = (q0 + gr) * ATP + kk * 8 + tig;
        int o1 = (q0 + gr + 8) * ATP + kk * 8 + tig;
        qf[kk][0] = Ps[o0];     qf[kk][1] = Ps[o1];
        qf[kk][2] = Ps[o0 + 4]; qf[kk][3] = Ps[o1 + 4];
    }

    float m0 = -3.0e38f, m1 = -3.0e38f, l0 = 0.f, l1 = 0.f;
    float o[8][4];
#pragma unroll
    for (int i = 0; i < 8; i++)
#pragma unroll
        for (int j = 0; j < 4; j++) o[i][j] = 0.f;

    // keys with kg > len are masked out -> only iterate tiles that intersect
    int nkt = S >> 6;
    int need = (len >> 6) + 1;
    if (need < nkt) nkt = need;

    for (int kt = 0; kt < nkt; kt++) {
        __syncthreads();
        // K tile: row-major [tok][d]
#pragma unroll
        for (int i = 0; i < 8; i++) {
            int idx = i * 128 + tid;
            int tok = idx >> 4, d4 = (idx & 15) * 4;
            float4 k = *(const float4*)(base
                + (size_t)(kt * 64 + tok) * (3 * D_) + D_ + h * 64 + d4);
            uint4 t;
            t.x = f2tf(k.x); t.y = f2tf(k.y); t.z = f2tf(k.z); t.w = f2tf(k.w);
            *(uint4*)&Ks[tok * ATP + d4] = t;
        }
        // V tile transposed: Vt[d][tok]
        {
            int d = tid & 63, tq0 = tid >> 6;
#pragma unroll
            for (int i = 0; i < 8; i++) {
                int tok = (tq0 * 8 + i) * 4;
                const float* vb = base + (size_t)(kt * 64 + tok) * (3 * D_)
                                  + 2 * D_ + h * 64 + d;
                uint4 t;
                t.x = f2tf(vb[0]);
                t.y = f2tf(vb[3 * D_]);
                t.z = f2tf(vb[6 * D_]);
                t.w = f2tf(vb[9 * D_]);
                *(uint4*)&Vt[d * ATP + tok] = t;
            }
        }
        __syncthreads();

        // ---- S = Q K^T ----
        float s[8][4];
#pragma unroll
        for (int nt = 0; nt < 8; nt++)
#pragma unroll
            for (int j = 0; j < 4; j++) s[nt][j] = 0.f;
#pragma unroll
        for (int kk = 0; kk < 8; kk++)
#pragma unroll
            for (int nt = 0; nt < 8; nt++) {
                int ob = (nt * 8 + gr) * ATP + kk * 8 + tig;
                mma8(s[nt], qf[kk], Ks[ob], Ks[ob + 4]);
            }

        // ---- mask + online softmax ----
        float mx0 = -3.0e38f, mx1 = -3.0e38f;
#pragma unroll
        for (int nt = 0; nt < 8; nt++) {
            int c0 = kt * 64 + nt * 8 + 2 * tig;
            if (c0 > len)     { s[nt][0] = -1.0e30f; s[nt][2] = -1.0e30f; }
            if (c0 + 1 > len) { s[nt][1] = -1.0e30f; s[nt][3] = -1.0e30f; }
            mx0 = fmaxf(mx0, fmaxf(s[nt][0], s[nt][1]));
            mx1 = fmaxf(mx1, fmaxf(s[nt][2], s[nt][3]));
        }
        mx0 = fmaxf(mx0, __shfl_xor_sync(0xffffffffu, mx0, 1));
        mx0 = fmaxf(mx0, __shfl_xor_sync(0xffffffffu, mx0, 2));
        mx1 = fmaxf(mx1, __shfl_xor_sync(0xffffffffu, mx1, 1));
        mx1 = fmaxf(mx1, __shfl_xor_sync(0xffffffffu, mx1, 2));
        float mn0 = fmaxf(m0, mx0), mn1 = fmaxf(m1, mx1);
        float sc0 = __expf(m0 - mn0), sc1 = __expf(m1 - mn1);
        float rs0 = 0.f, rs1 = 0.f;
#pragma unroll
        for (int nt = 0; nt < 8; nt++) {
            float p0 = __expf(s[nt][0] - mn0);
            float p1 = __expf(s[nt][1] - mn0);
            float p2 = __expf(s[nt][2] - mn1);
            float p3 = __expf(s[nt][3] - mn1);
            rs0 += p0 + p1; rs1 += p2 + p3;
            uint2 u0; u0.x = f2tf(p0); u0.y = f2tf(p1);
            uint2 u1; u1.x = f2tf(p2); u1.y = f2tf(p3);
            *(uint2*)&Ps[(q0 + gr) * ATP + nt * 8 + 2 * tig] = u0;
            *(uint2*)&Ps[(q0 + gr + 8) * ATP + nt * 8 + 2 * tig] = u1;
        }
        rs0 += __shfl_xor_sync(0xffffffffu, rs0, 1);
        rs0 += __shfl_xor_sync(0xffffffffu, rs0, 2);
        rs1 += __shfl_xor_sync(0xffffffffu, rs1, 1);
        rs1 += __shfl_xor_sync(0xffffffffu, rs1, 2);
        l0 = l0 * sc0 + rs0; l1 = l1 * sc1 + rs1;
        m0 = mn0; m1 = mn1;
#pragma unroll
        for (int nt = 0; nt < 8; nt++) {
            o[nt][0] *= sc0; o[nt][1] *= sc0;
            o[nt][2] *= sc1; o[nt][3] *= sc1;
        }
        __syncwarp();

        // ---- O += P V ----
#pragma unroll
        for (int kk = 0; kk < 8; kk++) {
            unsigned af[4];
            int o0i = (q0 + gr) * ATP + kk * 8 + tig;
            int o1i = (q0 + gr + 8) * ATP + kk * 8 + tig;
            af[0] = Ps[o0i];     af[1] = Ps[o1i];
            af[2] = Ps[o0i + 4]; af[3] = Ps[o1i + 4];
#pragma unroll
            for (int nt2 = 0; nt2 < 8; nt2++) {
                int ob = (nt2 * 8 + gr) * ATP + kk * 8 + tig;
                mma8(o[nt2], af, Vt[ob], Vt[ob + 4]);
            }
        }
    }

    float inv0 = 1.f / l0, inv1 = 1.f / l1;
    size_t r0 = (size_t)(b * S + qt * 64 + q0 + gr) * D_ + h * 64;
    size_t r1 = r0 + 8 * D_;
#pragma unroll
    for (int nt2 = 0; nt2 < 8; nt2++) {
        int col = nt2 * 8 + 2 * tig;
        ctx[r0 + col]     = o[nt2][0] * inv0;
        ctx[r0 + col + 1] = o[nt2][1] * inv0;
        ctx[r1 + col]     = o[nt2][2] * inv1;
        ctx[r1 + col + 1] = o[nt2][3] * inv1;
    }
}

// ---------------- layernorm (in place, D=512) -------------------------------
__global__ __launch_bounds__(128) void ln_k(float* __restrict__ x,
                                            const float* __restrict__ g,
                                            const float* __restrict__ bt)
{
    __shared__ float sm8[8];
    int row = blockIdx.x, tid = threadIdx.x;
    float4* xr = (float4*)(x + (size_t)row * D_);
    float4 v = xr[tid];
    float s = v.x + v.y + v.z + v.w;
#pragma unroll
    for (int o = 16; o; o >>= 1) s += __shfl_xor_sync(0xffffffffu, s, o);
    if ((tid & 31) == 0) sm8[tid >> 5] = s;
    __syncthreads();
    float mean = (sm8[0] + sm8[1] + sm8[2] + sm8[3]) * (1.f / (float)D_);
    float d0 = v.x - mean, d1 = v.y - mean, d2 = v.z - mean, d3 = v.w - mean;
    float q = d0 * d0 + d1 * d1 + d2 * d2 + d3 * d3;
#pragma unroll
    for (int o = 16; o; o >>= 1) q += __shfl_xor_sync(0xffffffffu, q, o);
    if ((tid & 31) == 0) sm8[4 + (tid >> 5)] = q;
    __syncthreads();
    float var = (sm8[4] + sm8[5] + sm8[6] + sm8[7]) * (1.f / (float)D_);
    float inv = rsqrtf(var + 1e-5f);
    float4 g4 = ((const float4*)g)[tid];
    float4 b4 = ((const float4*)bt)[tid];
    v.x = d0 * inv * g4.x + b4.x;
    v.y = d1 * inv * g4.y + b4.y;
    v.z = d2 * inv * g4.z + b4.z;
    v.w = d3 * inv * g4.w + b4.w;
    xr[tid] = v;
}

// ---------------- length regulator ------------------------------------------
__global__ void regidx_k(const int* __restrict__ dur, int* __restrict__ idx)
{
    __shared__ int cums[T_];
    int b = blockIdx.x, tid = threadIdx.x;
    cums[tid] = dur[b * T_ + tid];
    __syncthreads();
    if (tid == 0) {
        int a = 0;
        for (int t = 0; t < T_; t++) { a += cums[t]; cums[t] = a; }
    }
    __syncthreads();
    for (int f = tid; f < MEL_; f += T_) {
        int lo = 0, hi = T_;
        while (lo < hi) {
            int mid = (lo + hi) >> 1;
            if (cums[mid] <= f) lo = mid + 1; else hi = mid;
        }
        idx[b * MEL_ + f] = (lo > T_ - 1) ? (T_ - 1) : lo;
    }
}

__global__ void gather_k(const float* __restrict__ enc, const int* __restrict__ idx,
                         const int* __restrict__ mlen, float* __restrict__ out)
{
    int row = blockIdx.x;            // b*MEL + f
    int b = row >> 10, f = row & 1023;
    float keep = (f <= mlen[b]) ? 1.f : 0.f;
    int t = idx[row];
    int tid = threadIdx.x;
    float4 v = ((const float4*)(enc + (size_t)(b * T_ + t) * D_))[tid];
    v.x *= keep; v.y *= keep; v.z *= keep; v.w *= keep;
    ((float4*)(out + (size_t)row * D_))[tid] = v;
}

// ---------------- per-layer driver ------------------------------------------
template<int SLOG>
static void runLayerT(const float* const* W, int l, float* x, float* y,
                      const int* lens, float* gqkv, float* gctx, float* gh)
{
    const int S = 1 << SLOG;
    const int N = B_ * S;
    const float* wqkv = W[0]  + (size_t)l * D_ * 3 * D_;
    const float* bqkv = W[1]  + (size_t)l * 3 * D_;
    const float* wo   = W[2]  + (size_t)l * D_ * D_;
    const float* bo   = W[3]  + (size_t)l * D_;
    const float* l1g  = W[4]  + (size_t)l * D_;
    const float* l1b  = W[5]  + (size_t)l * D_;
    const float* c1w  = W[6]  + (size_t)l * 3 * D_ * INTER_;
    const float* c1b  = W[7]  + (size_t)l * INTER_;
    const float* c2w  = W[8]  + (size_t)l * 3 * INTER_ * D_;
    const float* c2b  = W[9]  + (size_t)l * D_;
    const float* l2g  = W[10] + (size_t)l * D_;
    const float* l2b  = W[11] + (size_t)l * D_;

    gemm_tc<0, 0, 0, false, false, false><<<dim3(12, N / 128), 128>>>(
        x, wqkv, bqkv, nullptr, gqkv, N, 3 * D_, D_);
    attn_tc<<<dim3(S / 64, B_ * H_), 128, ATTN_SMEM>>>(gqkv, lens, gctx, S);
    gemm_tc<0, 0, 0, false, true, false><<<dim3(4, N / 128), 128>>>(
        gctx, wo, bo, x, y, N, D_, D_);
    ln_k<<<N, 128>>>(y, l1g, l1b);
    gemm_tc<1, SLOG, 9, true, false, false><<<dim3(16, N / 128), 128>>>(
        y, c1w, c1b, nullptr, gh, N, INTER_, 3 * D_);
    gemm_tc<1, SLOG, 11, false, true, false><<<dim3(4, N / 128), 128>>>(
        gh, c2w, c2b, y, x, N, D_, 3 * INTER_);
    ln_k<<<N, 128>>>(x, l2g, l2b);
}

// ---------------- driver -----------------------------------------------------
extern "C" void kernel_launch(void* const* d_in, const int* in_sizes, int n_in,
                              void* d_out, int out_size)
{
    const int* tokens = (const int*)d_in[0];
    const int* tlen   = (const int*)d_in[1];
    const int* mlen   = (const int*)d_in[2];
    const int* dur    = (const int*)d_in[3];

    int ei = n_in - 27;
    if (ei < 0 || in_sizes[ei] != 256 * D_) {
        for (int i = 0; i < n_in; i++)
            if (in_sizes[i] == 256 * D_) { ei = i; break; }
    }
    const float* emb = (const float*)d_in[ei];
    const float* P[26];
    for (int i = 0; i < 26; i++) P[i] = (const float*)d_in[ei + 1 + i];

    float *gx, *gy, *gctx, *gqkv, *gh;
    int* gidx;
    cudaGetSymbolAddress((void**)&gx,   g_x);
    cudaGetSymbolAddress((void**)&gy,   g_y);
    cudaGetSymbolAddress((void**)&gctx, g_ctx);
    cudaGetSymbolAddress((void**)&gqkv, g_qkv);
    cudaGetSymbolAddress((void**)&gh,   g_h);
    cudaGetSymbolAddress((void**)&gidx, g_idx);

    cudaFuncSetAttribute(attn_tc, cudaFuncAttributeMaxDynamicSharedMemorySize,
                         ATTN_SMEM);

    embed_k<<<B_ * T_, 128>>>(tokens, emb, gx);

    for (int l = 0; l < L_; l++)
        runLayerT<8>(P, l, gx, gy, tlen, gqkv, gctx, gh);

    regidx_k<<<B_, T_>>>(dur, gidx);
    gather_k<<<B_ * MEL_, 128>>>(gx, gidx, mlen, gy);

    for (int l = 0; l < L_; l++)
        runLayerT<10>(P + 12, l, gy, gx, mlen, gqkv, gctx, gh);

    gemm_tc<0, 0, 0, false, false, true><<<dim3(1, (B_ * MEL_) / 128), 128>>>(
        gy, P[24], P[25], nullptr, (float*)d_out, B_ * MEL_, OUT_, D_);
}